// round 7
// baseline (speedup 1.0000x reference)
#include <cuda_runtime.h>
#include <math.h>
#include <stdint.h>

#define B_ 8
#define N_ 1024
#define C_ 768
#define H_ 12
#define D_ 64
#define M_ (B_*N_)   // 8192

// Scratch (allocation-free rule: __device__ globals)
__device__ float g_q[B_*H_*N_*D_];    // [B,H,N,D]
__device__ float g_k[B_*H_*N_*D_];
__device__ float g_v[B_*H_*N_*D_];
__device__ float g_att[M_*C_];        // [B,N,C] attention output

// ---------------------------------------------------------------------------
// mma.sync tf32 helpers (sm_80+ PTX — works on the compute_103 base target)
// ---------------------------------------------------------------------------
__device__ __forceinline__ uint32_t f2tf32(float f) {
  uint32_t u;
  asm("cvt.rna.tf32.f32 %0, %1;" : "=r"(u) : "f"(f));
  return u;
}

__device__ __forceinline__ void mma_tf32(float* d, const uint32_t* a, const uint32_t* b) {
  asm volatile(
    "mma.sync.aligned.m16n8k8.row.col.f32.tf32.tf32.f32 "
    "{%0,%1,%2,%3}, {%4,%5,%6,%7}, {%8,%9}, {%0,%1,%2,%3};"
    : "+f"(d[0]), "+f"(d[1]), "+f"(d[2]), "+f"(d[3])
    : "r"(a[0]), "r"(a[1]), "r"(a[2]), "r"(a[3]), "r"(b[0]), "r"(b[1]));
}

// ---------------------------------------------------------------------------
// tf32 tensor-core GEMM: Out[m][n] = sum_k A[m][k] * W[k][n] (+bias)
// CTA 128x128, 256 threads = 8 warps (4m x 2n), warp tile 32x64.
// 2 CTAs/SM (launch_bounds) for latency hiding.
// B global loads vectorized: 2 x LDG.128 along n per thread per stage.
// ---------------------------------------------------------------------------
template<int LDN, bool QKV>
__global__ __launch_bounds__(256, 2) void mma_gemm(
    const float* __restrict__ Ain, const float* __restrict__ W,
    const float* __restrict__ bias, float* __restrict__ Out)
{
  __shared__ uint32_t As[2048];   // 8KB
  __shared__ uint32_t Bs[2048];   // 8KB

  const int tid  = threadIdx.x;
  const int lane = tid & 31;
  const int w    = tid >> 5;
  const int wm   = w & 3;
  const int wn   = w >> 2;
  const int m0 = blockIdx.y * 128, n0 = blockIdx.x * 128;

  const float* A = QKV ? Ain : g_att;

  float acc[2][8][4];
#pragma unroll
  for (int i = 0; i < 2; i++)
#pragma unroll
    for (int j = 0; j < 8; j++)
#pragma unroll
      for (int q = 0; q < 4; q++) acc[i][j][q] = 0.f;

  // --- staging coordinates ---
  // A: idx = tid + it*256 in 0..511 ; row = idx>>2 (0..127), k4 = idx&3
  int a_row[2], a_k4[2], a_base[2];
  // B: idx = tid + it*256 ; k = idx>>5 (0..15), n4 = idx&31 (n = 4*n4)
  int b_k[2], b_n4[2], b_base[2];
#pragma unroll
  for (int it = 0; it < 2; it++) {
    const int ia = tid + it * 256;
    a_row[it] = ia >> 2;
    a_k4[it]  = ia & 3;
    {
      const int row = a_row[it], k4 = a_k4[it];
      const int kc = k4 >> 1;
      const int slot = ((row >> 3) & 1) | ((k4 & 1) << 1);
      const int mf = row >> 4;
      a_base[it] = (kc * 8 + mf) * 128 + (row & 7) * 16 + slot;
    }
    const int ib = tid + it * 256;
    b_k[it]  = ib >> 5;
    b_n4[it] = ib & 31;
    {
      const int k = b_k[it], n = b_n4[it] * 4;
      // word index for (k, n): ((k>>3)*16 + (n>>3))*64 + (n&7)*8 + (k&3)*2 + ((k>>2)&1)
      b_base[it] = ((k >> 3) * 16 + (n >> 3)) * 64 + (n & 7) * 8 + (k & 3) * 2 + ((k >> 2) & 1);
    }
  }

  float4 pa[2], pb[2];

  // prefetch stage 0
#pragma unroll
  for (int it = 0; it < 2; it++) {
    pa[it] = *(const float4*)&A[(size_t)(m0 + a_row[it]) * 768 + a_k4[it] * 4];
    pb[it] = *(const float4*)&W[(size_t)b_k[it] * LDN + n0 + b_n4[it] * 4];
  }

  for (int kt = 0; kt < 48; kt++) {
#pragma unroll
    for (int it = 0; it < 2; it++) {
      As[a_base[it] + 0]  = f2tf32(pa[it].x);
      As[a_base[it] + 4]  = f2tf32(pa[it].y);
      As[a_base[it] + 8]  = f2tf32(pa[it].z);
      As[a_base[it] + 12] = f2tf32(pa[it].w);
      // B: 4 consecutive n, same k; n&7 advances by 1 -> +8 words (nf bumps at n&7==7,
      // but n = 4*n4 so the 4 elements stay within one nf group of 8)
      Bs[b_base[it] + 0]  = f2tf32(pb[it].x);
      Bs[b_base[it] + 8]  = f2tf32(pb[it].y);
      Bs[b_base[it] + 16] = f2tf32(pb[it].z);
      Bs[b_base[it] + 24] = f2tf32(pb[it].w);
    }
    __syncthreads();

    if (kt < 47) {
      const int k0 = (kt + 1) * 16;
#pragma unroll
      for (int it = 0; it < 2; it++) {
        pa[it] = *(const float4*)&A[(size_t)(m0 + a_row[it]) * 768 + k0 + a_k4[it] * 4];
        pb[it] = *(const float4*)&W[(size_t)(k0 + b_k[it]) * LDN + n0 + b_n4[it] * 4];
      }
    }

#pragma unroll
    for (int kc = 0; kc < 2; kc++) {
      uint32_t af[2][4];
#pragma unroll
      for (int mf2 = 0; mf2 < 2; mf2++) {
        const uint32_t* p = &As[(kc * 8 + wm * 2 + mf2) * 128 + lane * 4];
        const uint4 v = *(const uint4*)p;
        af[mf2][0] = v.x; af[mf2][1] = v.y; af[mf2][2] = v.z; af[mf2][3] = v.w;
      }
#pragma unroll
      for (int nf = 0; nf < 8; nf++) {
        uint32_t bf[2];
        const uint32_t* p = &Bs[(kc * 16 + wn * 8 + nf) * 64 + lane * 2];
        bf[0] = p[0]; bf[1] = p[1];
        mma_tf32(acc[0][nf], af[0], bf);
        mma_tf32(acc[1][nf], af[1], bf);
      }
    }
    __syncthreads();
  }

  const int g = lane >> 2, tq = lane & 3;
#pragma unroll
  for (int mf2 = 0; mf2 < 2; mf2++) {
    const int r0 = m0 + wm * 32 + mf2 * 16 + g;
#pragma unroll
    for (int nf = 0; nf < 8; nf++) {
      const int col = n0 + wn * 64 + nf * 8 + tq * 2;
      const float bx = bias[col], by = bias[col + 1];
#pragma unroll
      for (int half = 0; half < 2; half++) {
        const int r = r0 + half * 8;
        float2 o;
        o.x = acc[mf2][nf][half * 2 + 0] + bx;
        o.y = acc[mf2][nf][half * 2 + 1] + by;
        if (QKV) {
          const int bb = r >> 10, t = r & 1023;
          const int which = col / 768;
          const int c = col - which * 768;
          const int hh = c >> 6, d = c & 63;
          float* dst = (which == 0) ? g_q : (which == 1) ? g_k : g_v;
          *(float2*)&dst[((size_t)((bb * 12 + hh) * 1024 + t)) * 64 + d] = o;
        } else {
          *(float2*)&Out[(size_t)r * 768 + col] = o;
        }
      }
    }
  }
}

// ---------------------------------------------------------------------------
// Tensor-core flash attention (tf32 mma.sync).
// CTA: 128 Q-rows of one (b,h); 8 warps; warp w owns rows [16w,16w+16).
// Q stays resident in smem (fragments re-read per kc); P gets its own region
// -> registers fit 2 CTAs/SM.  Smem 96KB dynamic:
//   Qs[8192] | Ps[8192] | Ks[4096] | Vs[4096]
// ---------------------------------------------------------------------------
__global__ __launch_bounds__(256, 2) void attn_mma(const int* __restrict__ pad_mask)
{
  extern __shared__ uint32_t smem[];
  uint32_t* Qs = smem;             // 32KB [kc8][mf8][128]
  uint32_t* Ps = smem + 8192;      // 32KB [kcP8][mf8][128]
  uint32_t* Ks = smem + 16384;     // 16KB [kc8][nf8][64]
  uint32_t* Vs = smem + 20480;     // 16KB [kcP8][nf8][64]

  const int tid  = threadIdx.x;
  const int lane = tid & 31;
  const int w    = tid >> 5;
  const int g    = lane >> 2;
  const int t    = lane & 3;
  const int bh = blockIdx.y;
  const int b  = bh / 12, h = bh % 12;
  const int q0 = blockIdx.x << 7;

  const float* Qg = g_q + (size_t)bh * (N_*D_) + (size_t)q0 * D_;
  const float* Kg = g_k + (size_t)bh * (N_*D_);
  const float* Vg = g_v + (size_t)bh * (N_*D_);

  // --- stage Q (128x64) into A-frag layout ---
#pragma unroll
  for (int it = 0; it < 8; it++) {
    const int idx = tid + it * 256;
    const int r = idx >> 4, d4 = idx & 15;
    const float4 qv = *(const float4*)&Qg[(size_t)r * 64 + d4 * 4];
    const int base = ((d4 >> 1) * 8 + (r >> 4)) * 128 + (r & 7) * 16
                   + (d4 & 1) * 2 + ((r >> 3) & 1);
    Qs[base + 0]  = f2tf32(qv.x);
    Qs[base + 4]  = f2tf32(qv.y);
    Qs[base + 8]  = f2tf32(qv.z);
    Qs[base + 12] = f2tf32(qv.w);
  }

  const bool mz0 = (pad_mask[b * N_ + q0 + w * 16 + g] == 0);
  const bool mz1 = (pad_mask[b * N_ + q0 + w * 16 + g + 8] == 0);

  float accO[8][4];
#pragma unroll
  for (int nf = 0; nf < 8; nf++)
#pragma unroll
    for (int j = 0; j < 4; j++) accO[nf][j] = 0.f;
  float rowM0 = -INFINITY, rowM1 = -INFINITY, rowL0 = 0.f, rowL1 = 0.f;

  for (int kt = 0; kt < 16; kt++) {
    __syncthreads();   // prev Ks/Vs reads done (and Q staging on kt=0)
    // --- stage K and V tiles (64 keys x 64 d each) ---
#pragma unroll
    for (int it = 0; it < 4; it++) {
      const int idx = tid + it * 256;
      const int r = idx >> 4, d4 = idx & 15;
      const float4 kv = *(const float4*)&Kg[(size_t)(kt * 64 + r) * 64 + d4 * 4];
      const int kb = ((d4 >> 1) * 8 + (r >> 3)) * 64 + (r & 7) * 8 + (d4 & 1);
      Ks[kb + 0] = f2tf32(kv.x);
      Ks[kb + 2] = f2tf32(kv.y);
      Ks[kb + 4] = f2tf32(kv.z);
      Ks[kb + 6] = f2tf32(kv.w);
      const float4 vv = *(const float4*)&Vg[(size_t)(kt * 64 + r) * 64 + d4 * 4];
      const int vb = ((r >> 3) * 8 + (d4 >> 1)) * 64 + (d4 & 1) * 32
                   + (r & 3) * 2 + ((r >> 2) & 1);
      Vs[vb + 0]  = f2tf32(vv.x);
      Vs[vb + 8]  = f2tf32(vv.y);
      Vs[vb + 16] = f2tf32(vv.z);
      Vs[vb + 24] = f2tf32(vv.w);
    }
    __syncthreads();

    // --- S = Q K^T : per warp 16x64 ---
    float accS[8][4];
#pragma unroll
    for (int nf = 0; nf < 8; nf++)
#pragma unroll
      for (int j = 0; j < 4; j++) accS[nf][j] = 0.f;
#pragma unroll
    for (int kc = 0; kc < 8; kc++) {
      uint32_t aQ[4];
      const uint4 qv = *(const uint4*)&Qs[(kc * 8 + w) * 128 + lane * 4];
      aQ[0] = qv.x; aQ[1] = qv.y; aQ[2] = qv.z; aQ[3] = qv.w;
#pragma unroll
      for (int nf = 0; nf < 8; nf++) {
        uint32_t bf[2];
        const uint32_t* p = &Ks[(kc * 8 + nf) * 64 + lane * 2];
        bf[0] = p[0]; bf[1] = p[1];
        mma_tf32(accS[nf], aQ, bf);
      }
    }

    // --- online softmax (warp-local; rows g and g+8) ---
    float mx0 = -INFINITY, mx1 = -INFINITY;
#pragma unroll
    for (int nf = 0; nf < 8; nf++) {
      accS[nf][0] = mz0 ? -INFINITY : accS[nf][0] * 0.125f;
      accS[nf][1] = mz0 ? -INFINITY : accS[nf][1] * 0.125f;
      accS[nf][2] = mz1 ? -INFINITY : accS[nf][2] * 0.125f;
      accS[nf][3] = mz1 ? -INFINITY : accS[nf][3] * 0.125f;
      mx0 = fmaxf(mx0, fmaxf(accS[nf][0], accS[nf][1]));
      mx1 = fmaxf(mx1, fmaxf(accS[nf][2], accS[nf][3]));
    }
#pragma unroll
    for (int o = 1; o <= 2; o <<= 1) {
      mx0 = fmaxf(mx0, __shfl_xor_sync(0xffffffffu, mx0, o));
      mx1 = fmaxf(mx1, __shfl_xor_sync(0xffffffffu, mx1, o));
    }
    const float mn0 = fmaxf(rowM0, mx0), mn1 = fmaxf(rowM1, mx1);
    const float fac0 = __expf(rowM0 - mn0), fac1 = __expf(rowM1 - mn1);
    rowM0 = mn0; rowM1 = mn1;
    float sum0 = 0.f, sum1 = 0.f;
#pragma unroll
    for (int nf = 0; nf < 8; nf++) {
      accS[nf][0] = __expf(accS[nf][0] - mn0);
      accS[nf][1] = __expf(accS[nf][1] - mn0);
      accS[nf][2] = __expf(accS[nf][2] - mn1);
      accS[nf][3] = __expf(accS[nf][3] - mn1);
      sum0 += accS[nf][0] + accS[nf][1];
      sum1 += accS[nf][2] + accS[nf][3];
    }
#pragma unroll
    for (int o = 1; o <= 2; o <<= 1) {
      sum0 += __shfl_xor_sync(0xffffffffu, sum0, o);
      sum1 += __shfl_xor_sync(0xffffffffu, sum1, o);
    }
    rowL0 = rowL0 * fac0 + sum0;
    rowL1 = rowL1 * fac1 + sum1;
#pragma unroll
    for (int nf = 0; nf < 8; nf++) {
      accO[nf][0] *= fac0; accO[nf][1] *= fac0;
      accO[nf][2] *= fac1; accO[nf][3] *= fac1;
    }

    // --- store P into A-frag layout (warp-private slices (nf*8+w)) ---
    const int f0 = ((2 * t) & 3) * 4 + ((2 * t) >> 2) * 2;
    const int f1 = ((2 * t + 1) & 3) * 4 + ((2 * t + 1) >> 2) * 2;
#pragma unroll
    for (int nf = 0; nf < 8; nf++) {
      const int base = (nf * 8 + w) * 128 + g * 16;
      Ps[base + f0]     = f2tf32(accS[nf][0]);
      Ps[base + f1]     = f2tf32(accS[nf][1]);
      Ps[base + f0 + 1] = f2tf32(accS[nf][2]);
      Ps[base + f1 + 1] = f2tf32(accS[nf][3]);
    }
    __syncwarp();

    // --- O += P V ---
#pragma unroll
    for (int kcP = 0; kcP < 8; kcP++) {
      uint32_t aP[4];
      const uint4 v = *(const uint4*)&Ps[(kcP * 8 + w) * 128 + lane * 4];
      aP[0] = v.x; aP[1] = v.y; aP[2] = v.z; aP[3] = v.w;
#pragma unroll
      for (int nf = 0; nf < 8; nf++) {
        uint32_t bf[2];
        const uint32_t* p = &Vs[(kcP * 8 + nf) * 64 + lane * 2];
        bf[0] = p[0]; bf[1] = p[1];
        mma_tf32(accO[nf], aP, bf);
      }
    }
    __syncwarp();
  }

  // --- epilogue: normalize + write to g_att[B,N,C] ---
  const float inv0 = 1.f / rowL0, inv1 = 1.f / rowL1;
  const int row0 = q0 + w * 16 + g;
#pragma unroll
  for (int nf = 0; nf < 8; nf++) {
    const int col = h * 64 + nf * 8 + t * 2;
    float2 o0, o1;
    o0.x = accO[nf][0] * inv0; o0.y = accO[nf][1] * inv0;
    o1.x = accO[nf][2] * inv1; o1.y = accO[nf][3] * inv1;
    *(float2*)&g_att[(size_t)(b * N_ + row0) * C_ + col]     = o0;
    *(float2*)&g_att[(size_t)(b * N_ + row0 + 8) * C_ + col] = o1;
  }
}

extern "C" void kernel_launch(void* const* d_in, const int* in_sizes, int n_in,
                              void* d_out, int out_size) {
  const float* x      = (const float*)d_in[0];
  const int*   pad    = (const int*)  d_in[1];
  const float* w_attn = (const float*)d_in[2];
  const float* b_attn = (const float*)d_in[3];
  const float* w_proj = (const float*)d_in[4];
  const float* b_proj = (const float*)d_in[5];
  float* out = (float*)d_out;

  cudaFuncSetAttribute(attn_mma, cudaFuncAttributeMaxDynamicSharedMemorySize, 98304);

  // 1) QKV projection (mma.sync tf32) + bias + scatter to [B,H,N,D]
  mma_gemm<2304, true><<<dim3(18, 64), 256>>>(x, w_attn, b_attn, nullptr);
  // 2) fused attention (mma.sync tf32 flash attention)
  attn_mma<<<dim3(8, 96), 256, 98304>>>(pad);
  // 3) output projection (mma.sync tf32) + bias -> d_out
  mma_gemm<768, false><<<dim3(6, 64), 256>>>(nullptr, w_proj, b_proj, out);
}

// round 8
// speedup vs baseline: 1.3165x; 1.3165x over previous
#include <cuda_runtime.h>
#include <math.h>
#include <stdint.h>

#define B_ 8
#define N_ 1024
#define C_ 768
#define H_ 12
#define D_ 64
#define M_ (B_*N_)   // 8192

// Scratch (allocation-free rule: __device__ globals)
__device__ float g_q[B_*H_*N_*D_];    // [B,H,N,D]
__device__ float g_k[B_*H_*N_*D_];
__device__ float g_v[B_*H_*N_*D_];
__device__ float g_att[M_*C_];        // [B,N,C] attention output

// ---------------------------------------------------------------------------
// mma.sync tf32 helpers (sm_80+ PTX — works on the compute_103 base target)
// ---------------------------------------------------------------------------
__device__ __forceinline__ uint32_t f2tf32(float f) {
  uint32_t u;
  asm("cvt.rna.tf32.f32 %0, %1;" : "=r"(u) : "f"(f));
  return u;
}

__device__ __forceinline__ void mma_tf32(float* d, const uint32_t* a, const uint32_t* b) {
  asm volatile(
    "mma.sync.aligned.m16n8k8.row.col.f32.tf32.tf32.f32 "
    "{%0,%1,%2,%3}, {%4,%5,%6,%7}, {%8,%9}, {%0,%1,%2,%3};"
    : "+f"(d[0]), "+f"(d[1]), "+f"(d[2]), "+f"(d[3])
    : "r"(a[0]), "r"(a[1]), "r"(a[2]), "r"(a[3]), "r"(b[0]), "r"(b[1]));
}

// ---------------------------------------------------------------------------
// tf32 tensor-core GEMM: Out[m][n] = sum_k A[m][k] * W[k][n] (+bias)
// CTA 128x128, 256 threads = 8 warps (4m x 2n), warp tile 32x64.
// DOUBLE-BUFFERED smem: one __syncthreads per K-stage; stores of stage kt+1
// and LDGs of stage kt+2 overlap the mma work on stage kt.
// (No min-blocks launch bound: natural 132 regs, 1 CTA/SM — the R7 reg-cap
//  spilled and saturated L1.)
// ---------------------------------------------------------------------------
template<int LDN, bool QKV>
__global__ __launch_bounds__(256) void mma_gemm(
    const float* __restrict__ Ain, const float* __restrict__ W,
    const float* __restrict__ bias, float* __restrict__ Out)
{
  __shared__ uint32_t As[2][2048];   // 16KB
  __shared__ uint32_t Bs[2][2048];   // 16KB

  const int tid  = threadIdx.x;
  const int lane = tid & 31;
  const int w    = tid >> 5;
  const int wm   = w & 3;
  const int wn   = w >> 2;
  const int m0 = blockIdx.y * 128, n0 = blockIdx.x * 128;

  const float* A = QKV ? Ain : g_att;

  float acc[2][8][4];
#pragma unroll
  for (int i = 0; i < 2; i++)
#pragma unroll
    for (int j = 0; j < 8; j++)
#pragma unroll
      for (int q = 0; q < 4; q++) acc[i][j][q] = 0.f;

  // --- per-thread staging coordinates (2 iters each for A and B) ---
  int a_row[2], a_k4[2], a_base[2];
  int b_n[2], b_k4[2], b_base[2];
#pragma unroll
  for (int it = 0; it < 2; it++) {
    const int ia = tid + it * 256;
    a_row[it] = ia >> 2;
    a_k4[it]  = ia & 3;
    {
      const int row = a_row[it], k4 = a_k4[it];
      const int kc = k4 >> 1;
      const int slot = ((row >> 3) & 1) | ((k4 & 1) << 1);
      const int mf = row >> 4;
      a_base[it] = (kc * 8 + mf) * 128 + (row & 7) * 16 + slot;
    }
    const int ib = tid + it * 256;
    b_n[it]  = ib & 127;
    b_k4[it] = ib >> 7;
    {
      const int n = b_n[it], k4 = b_k4[it];
      const int kc = k4 >> 1;
      const int nf = n >> 3;
      const int slot = k4 & 1;
      b_base[it] = (kc * 16 + nf) * 64 + (n & 7) * 8 + slot;
    }
  }

  float4 pa[2];
  float  pb[8];

  auto load_stage = [&](int kt) {
    const int k0 = kt * 16;
#pragma unroll
    for (int it = 0; it < 2; it++) {
      pa[it] = *(const float4*)&A[(size_t)(m0 + a_row[it]) * 768 + k0 + a_k4[it] * 4];
#pragma unroll
      for (int i = 0; i < 4; i++)
        pb[it * 4 + i] = W[(size_t)(k0 + b_k4[it] * 4 + i) * LDN + n0 + b_n[it]];
    }
  };
  auto store_stage = [&](int buf) {
#pragma unroll
    for (int it = 0; it < 2; it++) {
      As[buf][a_base[it] + 0]  = f2tf32(pa[it].x);
      As[buf][a_base[it] + 4]  = f2tf32(pa[it].y);
      As[buf][a_base[it] + 8]  = f2tf32(pa[it].z);
      As[buf][a_base[it] + 12] = f2tf32(pa[it].w);
      Bs[buf][b_base[it] + 0]  = f2tf32(pb[it * 4 + 0]);
      Bs[buf][b_base[it] + 2]  = f2tf32(pb[it * 4 + 1]);
      Bs[buf][b_base[it] + 4]  = f2tf32(pb[it * 4 + 2]);
      Bs[buf][b_base[it] + 6]  = f2tf32(pb[it * 4 + 3]);
    }
  };

  // prologue: stage 0 into buf0, prefetch stage 1 into regs
  load_stage(0);
  store_stage(0);
  load_stage(1);
  __syncthreads();

  for (int kt = 0; kt < 48; kt++) {
    const int cur = kt & 1, nxt = cur ^ 1;
    if (kt < 47) store_stage(nxt);      // overlaps compute on cur
    if (kt < 46) load_stage(kt + 2);    // LDG latency hidden behind compute

#pragma unroll
    for (int kc = 0; kc < 2; kc++) {
      uint32_t af[2][4];
#pragma unroll
      for (int mf2 = 0; mf2 < 2; mf2++) {
        const uint32_t* p = &As[cur][(kc * 8 + wm * 2 + mf2) * 128 + lane * 4];
        const uint4 v = *(const uint4*)p;
        af[mf2][0] = v.x; af[mf2][1] = v.y; af[mf2][2] = v.z; af[mf2][3] = v.w;
      }
#pragma unroll
      for (int nf = 0; nf < 8; nf++) {
        uint32_t bf[2];
        const uint32_t* p = &Bs[cur][(kc * 16 + wn * 8 + nf) * 64 + lane * 2];
        bf[0] = p[0]; bf[1] = p[1];
        mma_tf32(acc[0][nf], af[0], bf);
        mma_tf32(acc[1][nf], af[1], bf);
      }
    }
    __syncthreads();
  }

  // --- epilogue: bias + store (float2 per C reg-pair) ---
  const int g = lane >> 2, tq = lane & 3;
#pragma unroll
  for (int mf2 = 0; mf2 < 2; mf2++) {
    const int r0 = m0 + wm * 32 + mf2 * 16 + g;
#pragma unroll
    for (int nf = 0; nf < 8; nf++) {
      const int col = n0 + wn * 64 + nf * 8 + tq * 2;
      const float bx = bias[col], by = bias[col + 1];
#pragma unroll
      for (int half = 0; half < 2; half++) {
        const int r = r0 + half * 8;
        float2 o;
        o.x = acc[mf2][nf][half * 2 + 0] + bx;
        o.y = acc[mf2][nf][half * 2 + 1] + by;
        if (QKV) {
          const int bb = r >> 10, t = r & 1023;
          const int which = col / 768;
          const int c = col - which * 768;
          const int hh = c >> 6, d = c & 63;
          float* dst = (which == 0) ? g_q : (which == 1) ? g_k : g_v;
          *(float2*)&dst[((size_t)((bb * 12 + hh) * 1024 + t)) * 64 + d] = o;
        } else {
          *(float2*)&Out[(size_t)r * 768 + col] = o;
        }
      }
    }
  }
}

// ---------------------------------------------------------------------------
// Tensor-core flash attention (tf32 mma.sync) — exact R5 version (proven).
// CTA: 128 Q-rows of one (b,h); 8 warps; warp w owns rows [16w,16w+16).
// Smem (dynamic 64KB): QPs[8192] (Q then P) | Ks[4096] | Vs[4096].
// ---------------------------------------------------------------------------
__global__ __launch_bounds__(256) void attn_mma(const int* __restrict__ pad_mask)
{
  extern __shared__ uint32_t smem[];
  uint32_t* QPs = smem;            // 32KB
  uint32_t* Ks  = smem + 8192;     // 16KB
  uint32_t* Vs  = smem + 12288;    // 16KB

  const int tid  = threadIdx.x;
  const int lane = tid & 31;
  const int w    = tid >> 5;
  const int g    = lane >> 2;
  const int t    = lane & 3;
  const int bh = blockIdx.y;
  const int b  = bh / 12, h = bh % 12;
  const int q0 = blockIdx.x << 7;

  const float* Qg = g_q + (size_t)bh * (N_*D_) + (size_t)q0 * D_;
  const float* Kg = g_k + (size_t)bh * (N_*D_);
  const float* Vg = g_v + (size_t)bh * (N_*D_);

#pragma unroll
  for (int it = 0; it < 8; it++) {
    const int idx = tid + it * 256;
    const int r = idx >> 4, d4 = idx & 15;
    const float4 qv = *(const float4*)&Qg[(size_t)r * 64 + d4 * 4];
    const int base = ((d4 >> 1) * 8 + (r >> 4)) * 128 + (r & 7) * 16
                   + (d4 & 1) * 2 + ((r >> 3) & 1);
    QPs[base + 0]  = f2tf32(qv.x);
    QPs[base + 4]  = f2tf32(qv.y);
    QPs[base + 8]  = f2tf32(qv.z);
    QPs[base + 12] = f2tf32(qv.w);
  }
  __syncthreads();

  uint32_t aQ[8][4];
#pragma unroll
  for (int kc = 0; kc < 8; kc++) {
    const uint4 v = *(const uint4*)&QPs[(kc * 8 + w) * 128 + lane * 4];
    aQ[kc][0] = v.x; aQ[kc][1] = v.y; aQ[kc][2] = v.z; aQ[kc][3] = v.w;
  }

  const bool mz0 = (pad_mask[b * N_ + q0 + w * 16 + g] == 0);
  const bool mz1 = (pad_mask[b * N_ + q0 + w * 16 + g + 8] == 0);

  float accO[8][4];
#pragma unroll
  for (int nf = 0; nf < 8; nf++)
#pragma unroll
    for (int j = 0; j < 4; j++) accO[nf][j] = 0.f;
  float rowM0 = -INFINITY, rowM1 = -INFINITY, rowL0 = 0.f, rowL1 = 0.f;

  for (int kt = 0; kt < 16; kt++) {
    __syncthreads();
#pragma unroll
    for (int it = 0; it < 4; it++) {
      const int idx = tid + it * 256;
      const int r = idx >> 4, d4 = idx & 15;
      const float4 kv = *(const float4*)&Kg[(size_t)(kt * 64 + r) * 64 + d4 * 4];
      const int kb = ((d4 >> 1) * 8 + (r >> 3)) * 64 + (r & 7) * 8 + (d4 & 1);
      Ks[kb + 0] = f2tf32(kv.x);
      Ks[kb + 2] = f2tf32(kv.y);
      Ks[kb + 4] = f2tf32(kv.z);
      Ks[kb + 6] = f2tf32(kv.w);
      const float4 vv = *(const float4*)&Vg[(size_t)(kt * 64 + r) * 64 + d4 * 4];
      const int vb = ((r >> 3) * 8 + (d4 >> 1)) * 64 + (d4 & 1) * 32
                   + (r & 3) * 2 + ((r >> 2) & 1);
      Vs[vb + 0]  = f2tf32(vv.x);
      Vs[vb + 8]  = f2tf32(vv.y);
      Vs[vb + 16] = f2tf32(vv.z);
      Vs[vb + 24] = f2tf32(vv.w);
    }
    __syncthreads();

    float accS[8][4];
#pragma unroll
    for (int nf = 0; nf < 8; nf++)
#pragma unroll
      for (int j = 0; j < 4; j++) accS[nf][j] = 0.f;
#pragma unroll
    for (int kc = 0; kc < 8; kc++) {
#pragma unroll
      for (int nf = 0; nf < 8; nf++) {
        uint32_t bf[2];
        const uint32_t* p = &Ks[(kc * 8 + nf) * 64 + lane * 2];
        bf[0] = p[0]; bf[1] = p[1];
        mma_tf32(accS[nf], aQ[kc], bf);
      }
    }

    float mx0 = -INFINITY, mx1 = -INFINITY;
#pragma unroll
    for (int nf = 0; nf < 8; nf++) {
      accS[nf][0] = mz0 ? -INFINITY : accS[nf][0] * 0.125f;
      accS[nf][1] = mz0 ? -INFINITY : accS[nf][1] * 0.125f;
      accS[nf][2] = mz1 ? -INFINITY : accS[nf][2] * 0.125f;
      accS[nf][3] = mz1 ? -INFINITY : accS[nf][3] * 0.125f;
      mx0 = fmaxf(mx0, fmaxf(accS[nf][0], accS[nf][1]));
      mx1 = fmaxf(mx1, fmaxf(accS[nf][2], accS[nf][3]));
    }
#pragma unroll
    for (int o = 1; o <= 2; o <<= 1) {
      mx0 = fmaxf(mx0, __shfl_xor_sync(0xffffffffu, mx0, o));
      mx1 = fmaxf(mx1, __shfl_xor_sync(0xffffffffu, mx1, o));
    }
    const float mn0 = fmaxf(rowM0, mx0), mn1 = fmaxf(rowM1, mx1);
    const float fac0 = __expf(rowM0 - mn0), fac1 = __expf(rowM1 - mn1);
    rowM0 = mn0; rowM1 = mn1;
    float sum0 = 0.f, sum1 = 0.f;
#pragma unroll
    for (int nf = 0; nf < 8; nf++) {
      accS[nf][0] = __expf(accS[nf][0] - mn0);
      accS[nf][1] = __expf(accS[nf][1] - mn0);
      accS[nf][2] = __expf(accS[nf][2] - mn1);
      accS[nf][3] = __expf(accS[nf][3] - mn1);
      sum0 += accS[nf][0] + accS[nf][1];
      sum1 += accS[nf][2] + accS[nf][3];
    }
#pragma unroll
    for (int o = 1; o <= 2; o <<= 1) {
      sum0 += __shfl_xor_sync(0xffffffffu, sum0, o);
      sum1 += __shfl_xor_sync(0xffffffffu, sum1, o);
    }
    rowL0 = rowL0 * fac0 + sum0;
    rowL1 = rowL1 * fac1 + sum1;
#pragma unroll
    for (int nf = 0; nf < 8; nf++) {
      accO[nf][0] *= fac0; accO[nf][1] *= fac0;
      accO[nf][2] *= fac1; accO[nf][3] *= fac1;
    }

    const int f0 = ((2 * t) & 3) * 4 + ((2 * t) >> 2) * 2;
    const int f1 = ((2 * t + 1) & 3) * 4 + ((2 * t + 1) >> 2) * 2;
#pragma unroll
    for (int nf = 0; nf < 8; nf++) {
      const int base = (nf * 8 + w) * 128 + g * 16;
      QPs[base + f0]     = f2tf32(accS[nf][0]);
      QPs[base + f1]     = f2tf32(accS[nf][1]);
      QPs[base + f0 + 1] = f2tf32(accS[nf][2]);
      QPs[base + f1 + 1] = f2tf32(accS[nf][3]);
    }
    __syncwarp();

#pragma unroll
    for (int kcP = 0; kcP < 8; kcP++) {
      uint32_t aP[4];
      const uint4 v = *(const uint4*)&QPs[(kcP * 8 + w) * 128 + lane * 4];
      aP[0] = v.x; aP[1] = v.y; aP[2] = v.z; aP[3] = v.w;
#pragma unroll
      for (int nf = 0; nf < 8; nf++) {
        uint32_t bf[2];
        const uint32_t* p = &Vs[(kcP * 8 + nf) * 64 + lane * 2];
        bf[0] = p[0]; bf[1] = p[1];
        mma_tf32(accO[nf], aP, bf);
      }
    }
    __syncwarp();
  }

  const float inv0 = 1.f / rowL0, inv1 = 1.f / rowL1;
  const int row0 = q0 + w * 16 + g;
#pragma unroll
  for (int nf = 0; nf < 8; nf++) {
    const int col = h * 64 + nf * 8 + t * 2;
    float2 o0, o1;
    o0.x = accO[nf][0] * inv0; o0.y = accO[nf][1] * inv0;
    o1.x = accO[nf][2] * inv1; o1.y = accO[nf][3] * inv1;
    *(float2*)&g_att[(size_t)(b * N_ + row0) * C_ + col]     = o0;
    *(float2*)&g_att[(size_t)(b * N_ + row0 + 8) * C_ + col] = o1;
  }
}

extern "C" void kernel_launch(void* const* d_in, const int* in_sizes, int n_in,
                              void* d_out, int out_size) {
  const float* x      = (const float*)d_in[0];
  const int*   pad    = (const int*)  d_in[1];
  const float* w_attn = (const float*)d_in[2];
  const float* b_attn = (const float*)d_in[3];
  const float* w_proj = (const float*)d_in[4];
  const float* b_proj = (const float*)d_in[5];
  float* out = (float*)d_out;

  cudaFuncSetAttribute(attn_mma, cudaFuncAttributeMaxDynamicSharedMemorySize, 65536);

  // 1) QKV projection (mma.sync tf32) + bias + scatter to [B,H,N,D]
  mma_gemm<2304, true><<<dim3(18, 64), 256>>>(x, w_attn, b_attn, nullptr);
  // 2) fused attention (mma.sync tf32 flash attention)
  attn_mma<<<dim3(8, 96), 256, 65536>>>(pad);
  // 3) output projection (mma.sync tf32) + bias -> d_out
  mma_gemm<768, false><<<dim3(6, 64), 256>>>(nullptr, w_proj, b_proj, out);
}

// round 9
// speedup vs baseline: 2.2752x; 1.7282x over previous
#include <cuda_runtime.h>
#include <cuda_fp16.h>
#include <math.h>
#include <stdint.h>

#define B_ 8
#define N_ 1024
#define C_ 768
#define H_ 12
#define D_ 64
#define M_ (B_*N_)   // 8192

// Scratch (allocation-free rule: __device__ globals)
__device__ float g_q[B_*H_*N_*D_];    // [B,H,N,D]
__device__ float g_k[B_*H_*N_*D_];
__device__ float g_v[B_*H_*N_*D_];
__device__ float g_att[M_*C_];        // [B,N,C] attention output

// ---------------------------------------------------------------------------
// fp16 mma.sync helpers (m16n8k16, fp32 accumulate)
// Fragment layouts (PTX): lane = g*4 + t (g=lane>>2 row/col group, t=lane&3)
//   A (16x16): a0=(g,2t|2t+1) a1=(g+8,..) a2=(g,2t+8|9) a3=(g+8,2t+8|9)
//              -> regid = rowhi + 2*khi
//   B (16x8):  b0=(k=2t|2t+1, n=g) b1=(k=2t+8|9, n=g)  -> regid = khi
//   C (16x8):  c0,c1=(g, 2t|2t+1) c2,c3=(g+8, ..)      (same as tf32 path)
// ---------------------------------------------------------------------------
__device__ __forceinline__ uint32_t pack_h2(float x, float y) {
  __half2 h = __floats2half2_rn(x, y);   // low 16 = x (elem0), high = y
  return *reinterpret_cast<uint32_t*>(&h);
}

__device__ __forceinline__ void mma_f16(float* d, const uint32_t* a, const uint32_t* b) {
  asm volatile(
    "mma.sync.aligned.m16n8k16.row.col.f32.f16.f16.f32 "
    "{%0,%1,%2,%3}, {%4,%5,%6,%7}, {%8,%9}, {%0,%1,%2,%3};"
    : "+f"(d[0]), "+f"(d[1]), "+f"(d[2]), "+f"(d[3])
    : "r"(a[0]), "r"(a[1]), "r"(a[2]), "r"(a[3]), "r"(b[0]), "r"(b[1]));
}

// ---------------------------------------------------------------------------
// fp16 tensor-core GEMM: Out[m][n] = sum_k A[m][k] * W[k][n] (+bias)
// CTA 128x128, 8 warps (4m x 2n), warp tile 32x64, K staged 16/iter,
// double-buffered smem (one barrier per stage).
// Smem per buffer: A [mf(8)][128 w] 4KB, B [nf(16)][64 w] 4KB.
// ---------------------------------------------------------------------------
template<int LDN, bool QKV>
__global__ __launch_bounds__(256) void mma_gemm(
    const float* __restrict__ Ain, const float* __restrict__ W,
    const float* __restrict__ bias, float* __restrict__ Out)
{
  __shared__ uint32_t As[2][1024];   // 8KB total
  __shared__ uint32_t Bs[2][1024];   // 8KB total

  const int tid  = threadIdx.x;
  const int lane = tid & 31;
  const int w    = tid >> 5;
  const int wm   = w & 3;
  const int wn   = w >> 2;
  const int m0 = blockIdx.y * 128, n0 = blockIdx.x * 128;

  const float* A = QKV ? Ain : g_att;

  float acc[2][8][4];
#pragma unroll
  for (int i = 0; i < 2; i++)
#pragma unroll
    for (int j = 0; j < 8; j++)
#pragma unroll
      for (int q = 0; q < 4; q++) acc[i][j][q] = 0.f;

  // --- per-thread staging coordinates ---
  // A: ia in 0..511 ; row = ia>>2 (0..127), k4 = ia&3 (float4 at k=4*k4)
  int a_row[2], a_k4[2], a_base[2];
  // B: ib in 0..511 ; n = ib&127, k4 = ib>>7 (4 scalar k at 4*k4)
  int b_n[2], b_k4[2], b_base[2];
#pragma unroll
  for (int it = 0; it < 2; it++) {
    const int ia = tid + it * 256;
    a_row[it] = ia >> 2;
    a_k4[it]  = ia & 3;
    {
      const int row = a_row[it], k4 = a_k4[it];
      const int mf = row >> 4, gg = row & 7, rowhi = (row >> 3) & 1;
      const int khi = k4 >> 1, t0 = (k4 & 1) * 2;
      a_base[it] = mf * 128 + (gg * 4 + t0) * 4 + rowhi + 2 * khi;
    }
    const int ib = tid + it * 256;
    b_n[it]  = ib & 127;
    b_k4[it] = ib >> 7;
    {
      const int n = b_n[it], k4 = b_k4[it];
      const int nf = n >> 3, gg = n & 7;
      const int khi = k4 >> 1, t0 = (k4 & 1) * 2;
      b_base[it] = nf * 64 + (gg * 4 + t0) * 2 + khi;
    }
  }

  float4 pa[2];
  float  pb[8];

  auto load_stage = [&](int kt) {
    const int k0 = kt * 16;
#pragma unroll
    for (int it = 0; it < 2; it++) {
      pa[it] = *(const float4*)&A[(size_t)(m0 + a_row[it]) * 768 + k0 + a_k4[it] * 4];
#pragma unroll
      for (int i = 0; i < 4; i++)
        pb[it * 4 + i] = W[(size_t)(k0 + b_k4[it] * 4 + i) * LDN + n0 + b_n[it]];
    }
  };
  auto store_stage = [&](int buf) {
#pragma unroll
    for (int it = 0; it < 2; it++) {
      As[buf][a_base[it] + 0] = pack_h2(pa[it].x, pa[it].y);
      As[buf][a_base[it] + 4] = pack_h2(pa[it].z, pa[it].w);
      Bs[buf][b_base[it] + 0] = pack_h2(pb[it * 4 + 0], pb[it * 4 + 1]);
      Bs[buf][b_base[it] + 2] = pack_h2(pb[it * 4 + 2], pb[it * 4 + 3]);
    }
  };

  load_stage(0);
  store_stage(0);
  load_stage(1);
  __syncthreads();

  for (int kt = 0; kt < 48; kt++) {
    const int cur = kt & 1, nxt = cur ^ 1;
    if (kt < 47) store_stage(nxt);
    if (kt < 46) load_stage(kt + 2);

    uint32_t af[2][4];
#pragma unroll
    for (int mf2 = 0; mf2 < 2; mf2++) {
      const uint4 v = *(const uint4*)&As[cur][(wm * 2 + mf2) * 128 + lane * 4];
      af[mf2][0] = v.x; af[mf2][1] = v.y; af[mf2][2] = v.z; af[mf2][3] = v.w;
    }
#pragma unroll
    for (int nf = 0; nf < 8; nf++) {
      uint32_t bf[2];
      const uint32_t* p = &Bs[cur][(wn * 8 + nf) * 64 + lane * 2];
      bf[0] = p[0]; bf[1] = p[1];
      mma_f16(acc[0][nf], af[0], bf);
      mma_f16(acc[1][nf], af[1], bf);
    }
    __syncthreads();
  }

  // --- epilogue: bias + store (float2 per C reg-pair) ---
  const int g = lane >> 2, tq = lane & 3;
#pragma unroll
  for (int mf2 = 0; mf2 < 2; mf2++) {
    const int r0 = m0 + wm * 32 + mf2 * 16 + g;
#pragma unroll
    for (int nf = 0; nf < 8; nf++) {
      const int col = n0 + wn * 64 + nf * 8 + tq * 2;
      const float bx = bias[col], by = bias[col + 1];
#pragma unroll
      for (int half = 0; half < 2; half++) {
        const int r = r0 + half * 8;
        float2 o;
        o.x = acc[mf2][nf][half * 2 + 0] + bx;
        o.y = acc[mf2][nf][half * 2 + 1] + by;
        if (QKV) {
          const int bb = r >> 10, t = r & 1023;
          const int which = col / 768;
          const int c = col - which * 768;
          const int hh = c >> 6, d = c & 63;
          float* dst = (which == 0) ? g_q : (which == 1) ? g_k : g_v;
          *(float2*)&dst[((size_t)((bb * 12 + hh) * 1024 + t)) * 64 + d] = o;
        } else {
          *(float2*)&Out[(size_t)r * 768 + col] = o;
        }
      }
    }
  }
}

// ---------------------------------------------------------------------------
// fp16 tensor-core flash attention.
// CTA: 128 Q-rows of one (b,h); 8 warps; warp w owns rows [16w,16w+16)
// -> warp-local softmax.  48KB static smem:
//   Qs [kc4][mf8][128w] 16KB | Ps [kcP4][mf8][128w] 16KB
//   Ks [kc4][nf8][64w]   8KB | Vs [kcP4][nf8][64w]   8KB
// ---------------------------------------------------------------------------
__global__ __launch_bounds__(256) void attn_mma(const int* __restrict__ pad_mask)
{
  __shared__ uint32_t smem[12288];   // 48KB
  uint32_t* Qs = smem;               // 4096 words
  uint32_t* Ps = smem + 4096;        // 4096
  uint32_t* Ks = smem + 8192;        // 2048
  uint32_t* Vs = smem + 10240;       // 2048
  uint16_t* Vs16 = (uint16_t*)Vs;

  const int tid  = threadIdx.x;
  const int lane = tid & 31;
  const int w    = tid >> 5;
  const int g    = lane >> 2;
  const int t    = lane & 3;
  const int bh = blockIdx.y;
  const int b  = bh / 12, h = bh % 12;
  const int q0 = blockIdx.x << 7;

  const float* Qg = g_q + (size_t)bh * (N_*D_) + (size_t)q0 * D_;
  const float* Kg = g_k + (size_t)bh * (N_*D_);
  const float* Vg = g_v + (size_t)bh * (N_*D_);

  // --- stage Q (128x64) into A-frag layout, fp16 ---
#pragma unroll
  for (int it = 0; it < 8; it++) {
    const int idx = tid + it * 256;
    const int r = idx >> 4, d4 = idx & 15;
    const float4 qv = *(const float4*)&Qg[(size_t)r * 64 + d4 * 4];
    const int kc = d4 >> 2, k4 = d4 & 3;
    const int mf = r >> 4, gg = r & 7, rowhi = (r >> 3) & 1;
    const int khi = k4 >> 1, t0 = (k4 & 1) * 2;
    const int base = (kc * 8 + mf) * 128 + (gg * 4 + t0) * 4 + rowhi + 2 * khi;
    Qs[base + 0] = pack_h2(qv.x, qv.y);
    Qs[base + 4] = pack_h2(qv.z, qv.w);
  }
  __syncthreads();

  // hoist Q fragments (warp-private mf = w)
  uint32_t aQ[4][4];
#pragma unroll
  for (int kc = 0; kc < 4; kc++) {
    const uint4 v = *(const uint4*)&Qs[(kc * 8 + w) * 128 + lane * 4];
    aQ[kc][0] = v.x; aQ[kc][1] = v.y; aQ[kc][2] = v.z; aQ[kc][3] = v.w;
  }

  const bool mz0 = (pad_mask[b * N_ + q0 + w * 16 + g] == 0);
  const bool mz1 = (pad_mask[b * N_ + q0 + w * 16 + g + 8] == 0);

  float accO[8][4];
#pragma unroll
  for (int nf = 0; nf < 8; nf++)
#pragma unroll
    for (int j = 0; j < 4; j++) accO[nf][j] = 0.f;
  float rowM0 = -INFINITY, rowM1 = -INFINITY, rowL0 = 0.f, rowL1 = 0.f;

  for (int kt = 0; kt < 16; kt++) {
    __syncthreads();   // prev Ks/Vs reads done
    // --- stage K and V tiles (64 keys x 64 d each) ---
#pragma unroll
    for (int it = 0; it < 4; it++) {
      const int idx = tid + it * 256;
      const int r = idx >> 4, d4 = idx & 15;
      // K: B-frag, k=d, n=key
      const float4 kv = *(const float4*)&Kg[(size_t)(kt * 64 + r) * 64 + d4 * 4];
      {
        const int kc = d4 >> 2, k4 = d4 & 3;
        const int nf = r >> 3, gn = r & 7;
        const int khi = k4 >> 1, t0 = (k4 & 1) * 2;
        const int kb = (kc * 8 + nf) * 64 + (gn * 4 + t0) * 2 + khi;
        Ks[kb + 0] = pack_h2(kv.x, kv.y);
        Ks[kb + 2] = pack_h2(kv.z, kv.w);
      }
      // V: B-frag, k=key, n=d  (scatter 4 halves)
      const float4 vv = *(const float4*)&Vg[(size_t)(kt * 64 + r) * 64 + d4 * 4];
      {
        const int kcP = r >> 4;
        const int p15 = (r & 15) >> 1, o = r & 1;
        const int tt = p15 & 3, khi = p15 >> 2;
        const int d0 = d4 * 4;
        const float vf[4] = { vv.x, vv.y, vv.z, vv.w };
#pragma unroll
        for (int i = 0; i < 4; i++) {
          const int d = d0 + i;
          const int word = (kcP * 8 + (d >> 3)) * 64 + ((d & 7) * 4 + tt) * 2 + khi;
          Vs16[word * 2 + o] = __half_as_ushort(__float2half_rn(vf[i]));
        }
      }
    }
    __syncthreads();

    // --- S = Q K^T : per warp 16x64, 4 kc x 8 nf ---
    float accS[8][4];
#pragma unroll
    for (int nf = 0; nf < 8; nf++)
#pragma unroll
      for (int j = 0; j < 4; j++) accS[nf][j] = 0.f;
#pragma unroll
    for (int kc = 0; kc < 4; kc++) {
#pragma unroll
      for (int nf = 0; nf < 8; nf++) {
        uint32_t bf[2];
        const uint32_t* p = &Ks[(kc * 8 + nf) * 64 + lane * 2];
        bf[0] = p[0]; bf[1] = p[1];
        mma_f16(accS[nf], aQ[kc], bf);
      }
    }

    // --- online softmax (warp-local; rows g and g+8) ---
    float mx0 = -INFINITY, mx1 = -INFINITY;
#pragma unroll
    for (int nf = 0; nf < 8; nf++) {
      accS[nf][0] = mz0 ? -INFINITY : accS[nf][0] * 0.125f;
      accS[nf][1] = mz0 ? -INFINITY : accS[nf][1] * 0.125f;
      accS[nf][2] = mz1 ? -INFINITY : accS[nf][2] * 0.125f;
      accS[nf][3] = mz1 ? -INFINITY : accS[nf][3] * 0.125f;
      mx0 = fmaxf(mx0, fmaxf(accS[nf][0], accS[nf][1]));
      mx1 = fmaxf(mx1, fmaxf(accS[nf][2], accS[nf][3]));
    }
#pragma unroll
    for (int o = 1; o <= 2; o <<= 1) {
      mx0 = fmaxf(mx0, __shfl_xor_sync(0xffffffffu, mx0, o));
      mx1 = fmaxf(mx1, __shfl_xor_sync(0xffffffffu, mx1, o));
    }
    const float mn0 = fmaxf(rowM0, mx0), mn1 = fmaxf(rowM1, mx1);
    const float fac0 = __expf(rowM0 - mn0), fac1 = __expf(rowM1 - mn1);
    rowM0 = mn0; rowM1 = mn1;
    float sum0 = 0.f, sum1 = 0.f;
#pragma unroll
    for (int nf = 0; nf < 8; nf++) {
      accS[nf][0] = __expf(accS[nf][0] - mn0);
      accS[nf][1] = __expf(accS[nf][1] - mn0);
      accS[nf][2] = __expf(accS[nf][2] - mn1);
      accS[nf][3] = __expf(accS[nf][3] - mn1);
      sum0 += accS[nf][0] + accS[nf][1];
      sum1 += accS[nf][2] + accS[nf][3];
    }
#pragma unroll
    for (int o = 1; o <= 2; o <<= 1) {
      sum0 += __shfl_xor_sync(0xffffffffu, sum0, o);
      sum1 += __shfl_xor_sync(0xffffffffu, sum1, o);
    }
    rowL0 = rowL0 * fac0 + sum0;
    rowL1 = rowL1 * fac1 + sum1;
#pragma unroll
    for (int nf = 0; nf < 8; nf++) {
      accO[nf][0] *= fac0; accO[nf][1] *= fac0;
      accO[nf][2] *= fac1; accO[nf][3] *= fac1;
    }

    // --- store P (A-frag, fp16, warp-private mf = w) ---
    // key col = 8nf + 2t(+1): kcP = nf>>1, khi = nf&1, t' = t, lane' = lane
#pragma unroll
    for (int nf = 0; nf < 8; nf++) {
      const int word = ((nf >> 1) * 8 + w) * 128 + lane * 4 + (nf & 1) * 2;
      Ps[word + 0] = pack_h2(accS[nf][0], accS[nf][1]);   // rowhi=0
      Ps[word + 1] = pack_h2(accS[nf][2], accS[nf][3]);   // rowhi=1
    }
    __syncwarp();

    // --- O += P V : 4 kcP x 8 nf ---
#pragma unroll
    for (int kcP = 0; kcP < 4; kcP++) {
      uint32_t aP[4];
      const uint4 v = *(const uint4*)&Ps[(kcP * 8 + w) * 128 + lane * 4];
      aP[0] = v.x; aP[1] = v.y; aP[2] = v.z; aP[3] = v.w;
#pragma unroll
      for (int nf = 0; nf < 8; nf++) {
        uint32_t bf[2];
        const uint32_t* p = &Vs[(kcP * 8 + nf) * 64 + lane * 2];
        bf[0] = p[0]; bf[1] = p[1];
        mma_f16(accO[nf], aP, bf);
      }
    }
    __syncwarp();
  }

  // --- epilogue: normalize + write to g_att[B,N,C] ---
  const float inv0 = 1.f / rowL0, inv1 = 1.f / rowL1;
  const int row0 = q0 + w * 16 + g;
#pragma unroll
  for (int nf = 0; nf < 8; nf++) {
    const int col = h * 64 + nf * 8 + t * 2;
    float2 o0, o1;
    o0.x = accO[nf][0] * inv0; o0.y = accO[nf][1] * inv0;
    o1.x = accO[nf][2] * inv1; o1.y = accO[nf][3] * inv1;
    *(float2*)&g_att[(size_t)(b * N_ + row0) * C_ + col]     = o0;
    *(float2*)&g_att[(size_t)(b * N_ + row0 + 8) * C_ + col] = o1;
  }
}

extern "C" void kernel_launch(void* const* d_in, const int* in_sizes, int n_in,
                              void* d_out, int out_size) {
  const float* x      = (const float*)d_in[0];
  const int*   pad    = (const int*)  d_in[1];
  const float* w_attn = (const float*)d_in[2];
  const float* b_attn = (const float*)d_in[3];
  const float* w_proj = (const float*)d_in[4];
  const float* b_proj = (const float*)d_in[5];
  float* out = (float*)d_out;

  // 1) QKV projection (fp16 mma) + bias + scatter to [B,H,N,D]
  mma_gemm<2304, true><<<dim3(18, 64), 256>>>(x, w_attn, b_attn, nullptr);
  // 2) fused attention (fp16 mma flash attention)
  attn_mma<<<dim3(8, 96), 256>>>(pad);
  // 3) output projection (fp16 mma) + bias -> d_out
  mma_gemm<768, false><<<dim3(6, 64), 256>>>(nullptr, w_proj, b_proj, out);
}

// round 10
// speedup vs baseline: 3.0152x; 1.3252x over previous
#include <cuda_runtime.h>
#include <cuda_fp16.h>
#include <math.h>
#include <stdint.h>

#define B_ 8
#define N_ 1024
#define C_ 768
#define H_ 12
#define D_ 64
#define M_ (B_*N_)   // 8192

// Scratch (allocation-free rule: __device__ globals), fp16 operands
__device__ __align__(16) __half g_x16[M_*C_];        // x, row-major [m][768]
__device__ __align__(16) __half g_wa16[3*C_*C_];     // w_attn^T [2304][768]
__device__ __align__(16) __half g_wp16[C_*C_];       // w_proj^T [768][768]
__device__ __align__(16) __half g_q16[B_*H_*N_*D_];  // [B,H,N,D]
__device__ __align__(16) __half g_k16[B_*H_*N_*D_];
__device__ __align__(16) __half g_v16[B_*H_*N_*D_];
__device__ __align__(16) __half g_att16[M_*C_];      // [B,N,C]

__device__ __forceinline__ uint32_t pack_h2(float x, float y) {
  __half2 h = __floats2half2_rn(x, y);
  return *reinterpret_cast<uint32_t*>(&h);
}

__device__ __forceinline__ void mma_f16(float* d, const uint32_t* a, const uint32_t* b) {
  asm volatile(
    "mma.sync.aligned.m16n8k16.row.col.f32.f16.f16.f32 "
    "{%0,%1,%2,%3}, {%4,%5,%6,%7}, {%8,%9}, {%0,%1,%2,%3};"
    : "+f"(d[0]), "+f"(d[1]), "+f"(d[2]), "+f"(d[3])
    : "r"(a[0]), "r"(a[1]), "r"(a[2]), "r"(a[3]), "r"(b[0]), "r"(b[1]));
}

// ---------------------------------------------------------------------------
// Prep kernels: fp32 -> fp16 convert / transpose (run once per launch)
// ---------------------------------------------------------------------------
__global__ void cvt_x_kernel(const float* __restrict__ x) {
  const int i = blockIdx.x * 256 + threadIdx.x;     // one float4 per thread
  const float4 v = ((const float4*)x)[i];
  uint2 o;
  o.x = pack_h2(v.x, v.y);
  o.y = pack_h2(v.z, v.w);
  ((uint2*)g_x16)[i] = o;
}

template<bool ATTN>   // src [rows=768(k)][cols(n)] -> dst fp16 [n][k]
__global__ void transpose_h_kernel(const float* __restrict__ src, int cols) {
  __shared__ float tb[32][33];
  __half* dst = ATTN ? g_wa16 : g_wp16;
  const int cb = blockIdx.x * 32, rb = blockIdx.y * 32;
  const int x = threadIdx.x, y = threadIdx.y;
#pragma unroll
  for (int i = 0; i < 32; i += 8)
    tb[y + i][x] = src[(size_t)(rb + y + i) * cols + cb + x];
  __syncthreads();
#pragma unroll
  for (int i = 0; i < 32; i += 8)
    dst[(size_t)(cb + y + i) * 768 + rb + x] = __float2half_rn(tb[x][y + i]);
}

// ---------------------------------------------------------------------------
// fp16 tensor-core GEMM: Out[m][n] = sum_k A16[m][k] * W16[n][k] (+bias)
// CTA 128x128, 8 warps (4m x 2n), K=16/stage, double-buffered.
// Both operands K-contiguous fp16: one LDG.128 = four fragment words
// (k-pairs), stored with 4 STS.32 — no conversion in the hot loop.
// ---------------------------------------------------------------------------
template<bool QKV>
__global__ __launch_bounds__(256, 2) void mma_gemm(
    const float* __restrict__ bias, float* __restrict__ Out)
{
  __shared__ uint32_t As[2][1024];   // 8KB
  __shared__ uint32_t Bs[2][1024];   // 8KB

  const int tid  = threadIdx.x;
  const int lane = tid & 31;
  const int w    = tid >> 5;
  const int wm   = w & 3;
  const int wn   = w >> 2;
  const int m0 = blockIdx.y * 128, n0 = blockIdx.x * 128;

  const __half* A16 = QKV ? g_x16 : g_att16;
  const __half* W16 = QKV ? g_wa16 : g_wp16;

  float acc[2][8][4];
#pragma unroll
  for (int i = 0; i < 2; i++)
#pragma unroll
    for (int j = 0; j < 8; j++)
#pragma unroll
      for (int q = 0; q < 4; q++) acc[i][j][q] = 0.f;

  // staging: row/n = tid>>1, k8 = tid&1 (8 halves at k = 8*k8 within stage)
  const int s_row = tid >> 1, s_k8 = tid & 1;
  const int a_base = (s_row >> 4) * 128 + (s_row & 7) * 16 + ((s_row >> 3) & 1) + 2 * s_k8;
  const int b_base = (s_row >> 3) * 64 + (s_row & 7) * 8 + s_k8;

  const __half* aptr = A16 + (size_t)(m0 + s_row) * 768 + s_k8 * 8;
  const __half* bptr = W16 + (size_t)(n0 + s_row) * 768 + s_k8 * 8;

  uint4 pa, pb;
  auto load_stage = [&](int kt) {
    pa = *(const uint4*)(aptr + kt * 16);
    pb = *(const uint4*)(bptr + kt * 16);
  };
  auto store_stage = [&](int buf) {
    As[buf][a_base + 0]  = pa.x;
    As[buf][a_base + 4]  = pa.y;
    As[buf][a_base + 8]  = pa.z;
    As[buf][a_base + 12] = pa.w;
    Bs[buf][b_base + 0]  = pb.x;
    Bs[buf][b_base + 2]  = pb.y;
    Bs[buf][b_base + 4]  = pb.z;
    Bs[buf][b_base + 6]  = pb.w;
  };

  load_stage(0);
  store_stage(0);
  load_stage(1);
  __syncthreads();

  for (int kt = 0; kt < 48; kt++) {
    const int cur = kt & 1, nxt = cur ^ 1;
    if (kt < 47) store_stage(nxt);
    if (kt < 46) load_stage(kt + 2);

    uint32_t af[2][4];
#pragma unroll
    for (int mf2 = 0; mf2 < 2; mf2++) {
      const uint4 v = *(const uint4*)&As[cur][(wm * 2 + mf2) * 128 + lane * 4];
      af[mf2][0] = v.x; af[mf2][1] = v.y; af[mf2][2] = v.z; af[mf2][3] = v.w;
    }
#pragma unroll
    for (int nf = 0; nf < 8; nf++) {
      uint32_t bf[2];
      const uint32_t* p = &Bs[cur][(wn * 8 + nf) * 64 + lane * 2];
      bf[0] = p[0]; bf[1] = p[1];
      mma_f16(acc[0][nf], af[0], bf);
      mma_f16(acc[1][nf], af[1], bf);
    }
    __syncthreads();
  }

  // --- epilogue ---
  const int g = lane >> 2, tq = lane & 3;
#pragma unroll
  for (int mf2 = 0; mf2 < 2; mf2++) {
    const int r0 = m0 + wm * 32 + mf2 * 16 + g;
#pragma unroll
    for (int nf = 0; nf < 8; nf++) {
      const int col = n0 + wn * 64 + nf * 8 + tq * 2;
      const float bx = bias[col], by = bias[col + 1];
#pragma unroll
      for (int half_ = 0; half_ < 2; half_++) {
        const int r = r0 + half_ * 8;
        const float ox = acc[mf2][nf][half_ * 2 + 0] + bx;
        const float oy = acc[mf2][nf][half_ * 2 + 1] + by;
        if (QKV) {
          const int bb = r >> 10, t = r & 1023;
          const int which = col / 768;
          const int c = col - which * 768;
          const int hh = c >> 6, d = c & 63;
          __half* dst = (which == 0) ? g_q16 : (which == 1) ? g_k16 : g_v16;
          const size_t idx = ((size_t)((bb * 12 + hh) * 1024 + t)) * 64 + d;
          ((uint32_t*)dst)[idx >> 1] = pack_h2(ox, oy);
        } else {
          float2 o; o.x = ox; o.y = oy;
          *(float2*)&Out[(size_t)r * 768 + col] = o;
        }
      }
    }
  }
}

// ---------------------------------------------------------------------------
// fp16 tensor-core flash attention (fp16 Q/K/V in global).
// CTA: 128 Q-rows of one (b,h); 8 warps; warp w owns rows [16w,16w+16).
// 48KB static smem: Qs 16KB | Ps 16KB | Ks 8KB | Vs 8KB.
// ---------------------------------------------------------------------------
__global__ __launch_bounds__(256) void attn_mma(const int* __restrict__ pad_mask)
{
  __shared__ uint32_t smem[12288];   // 48KB
  uint32_t* Qs = smem;               // [kc4][mf8][128w]
  uint32_t* Ps = smem + 4096;        // [kcP4][mf8][128w]
  uint32_t* Ks = smem + 8192;        // [kc4][nf8][64w]
  uint32_t* Vs = smem + 10240;       // [kcP4][nf8][64w]
  uint16_t* Vs16 = (uint16_t*)Vs;

  const int tid  = threadIdx.x;
  const int lane = tid & 31;
  const int w    = tid >> 5;
  const int g    = lane >> 2;
  const int t    = lane & 3;
  const int bh = blockIdx.y;
  const int b  = bh / 12, h = bh % 12;
  const int q0 = blockIdx.x << 7;

  const __half* Qg = g_q16 + (size_t)bh * (N_*D_) + (size_t)q0 * D_;
  const __half* Kg = g_k16 + (size_t)bh * (N_*D_);
  const __half* Vg = g_v16 + (size_t)bh * (N_*D_);

  // --- stage Q (128x64 halves) into A-frag layout ---
#pragma unroll
  for (int it = 0; it < 4; it++) {
    const int idx = tid + it * 256;      // 0..1023
    const int r = idx >> 3, d8 = idx & 7;
    const uint4 qv = *(const uint4*)(Qg + (size_t)r * 64 + d8 * 8);
    const int kc = d8 >> 1, khi = d8 & 1;
    const int base = (kc * 8 + (r >> 4)) * 128 + (r & 7) * 16 + ((r >> 3) & 1) + 2 * khi;
    Qs[base + 0]  = qv.x;
    Qs[base + 4]  = qv.y;
    Qs[base + 8]  = qv.z;
    Qs[base + 12] = qv.w;
  }
  __syncthreads();

  // hoist Q fragments (warp-private mf = w)
  uint32_t aQ[4][4];
#pragma unroll
  for (int kc = 0; kc < 4; kc++) {
    const uint4 v = *(const uint4*)&Qs[(kc * 8 + w) * 128 + lane * 4];
    aQ[kc][0] = v.x; aQ[kc][1] = v.y; aQ[kc][2] = v.z; aQ[kc][3] = v.w;
  }

  const bool mz0 = (pad_mask[b * N_ + q0 + w * 16 + g] == 0);
  const bool mz1 = (pad_mask[b * N_ + q0 + w * 16 + g + 8] == 0);

  float accO[8][4];
#pragma unroll
  for (int nf = 0; nf < 8; nf++)
#pragma unroll
    for (int j = 0; j < 4; j++) accO[nf][j] = 0.f;
  float rowM0 = -INFINITY, rowM1 = -INFINITY, rowL0 = 0.f, rowL1 = 0.f;

  for (int kt = 0; kt < 16; kt++) {
    __syncthreads();
    // --- stage K and V tiles (64 keys x 64 d, fp16) ---
#pragma unroll
    for (int it = 0; it < 2; it++) {
      const int idx = tid + it * 256;    // 0..511
      const int r = idx >> 3, d8 = idx & 7;
      // K: B-frag, k=d, n=key
      const uint4 kv = *(const uint4*)(Kg + (size_t)(kt * 64 + r) * 64 + d8 * 8);
      {
        const int kc = d8 >> 1, khi = d8 & 1;
        const int kb = (kc * 8 + (r >> 3)) * 64 + (r & 7) * 8 + khi;
        Ks[kb + 0] = kv.x;
        Ks[kb + 2] = kv.y;
        Ks[kb + 4] = kv.z;
        Ks[kb + 6] = kv.w;
      }
      // V: B-frag, k=key, n=d (scatter 8 halves)
      const uint4 vv = *(const uint4*)(Vg + (size_t)(kt * 64 + r) * 64 + d8 * 8);
      {
        const int kcP = r >> 4;
        const int khi = (r & 15) >> 3, tt = (r & 7) >> 1, o = r & 1;
        const uint16_t* pv = (const uint16_t*)&vv;
#pragma unroll
        for (int i = 0; i < 8; i++) {
          const int word = (kcP * 8 + d8) * 64 + i * 8 + tt * 2 + khi;
          Vs16[word * 2 + o] = pv[i];
        }
      }
    }
    __syncthreads();

    // --- S = Q K^T ---
    float accS[8][4];
#pragma unroll
    for (int nf = 0; nf < 8; nf++)
#pragma unroll
      for (int j = 0; j < 4; j++) accS[nf][j] = 0.f;
#pragma unroll
    for (int kc = 0; kc < 4; kc++) {
#pragma unroll
      for (int nf = 0; nf < 8; nf++) {
        uint32_t bf[2];
        const uint32_t* p = &Ks[(kc * 8 + nf) * 64 + lane * 2];
        bf[0] = p[0]; bf[1] = p[1];
        mma_f16(accS[nf], aQ[kc], bf);
      }
    }

    // --- online softmax (warp-local; rows g and g+8) ---
    float mx0 = -INFINITY, mx1 = -INFINITY;
#pragma unroll
    for (int nf = 0; nf < 8; nf++) {
      accS[nf][0] = mz0 ? -INFINITY : accS[nf][0] * 0.125f;
      accS[nf][1] = mz0 ? -INFINITY : accS[nf][1] * 0.125f;
      accS[nf][2] = mz1 ? -INFINITY : accS[nf][2] * 0.125f;
      accS[nf][3] = mz1 ? -INFINITY : accS[nf][3] * 0.125f;
      mx0 = fmaxf(mx0, fmaxf(accS[nf][0], accS[nf][1]));
      mx1 = fmaxf(mx1, fmaxf(accS[nf][2], accS[nf][3]));
    }
#pragma unroll
    for (int o = 1; o <= 2; o <<= 1) {
      mx0 = fmaxf(mx0, __shfl_xor_sync(0xffffffffu, mx0, o));
      mx1 = fmaxf(mx1, __shfl_xor_sync(0xffffffffu, mx1, o));
    }
    const float mn0 = fmaxf(rowM0, mx0), mn1 = fmaxf(rowM1, mx1);
    const float fac0 = __expf(rowM0 - mn0), fac1 = __expf(rowM1 - mn1);
    rowM0 = mn0; rowM1 = mn1;
    float sum0 = 0.f, sum1 = 0.f;
#pragma unroll
    for (int nf = 0; nf < 8; nf++) {
      accS[nf][0] = __expf(accS[nf][0] - mn0);
      accS[nf][1] = __expf(accS[nf][1] - mn0);
      accS[nf][2] = __expf(accS[nf][2] - mn1);
      accS[nf][3] = __expf(accS[nf][3] - mn1);
      sum0 += accS[nf][0] + accS[nf][1];
      sum1 += accS[nf][2] + accS[nf][3];
    }
#pragma unroll
    for (int o = 1; o <= 2; o <<= 1) {
      sum0 += __shfl_xor_sync(0xffffffffu, sum0, o);
      sum1 += __shfl_xor_sync(0xffffffffu, sum1, o);
    }
    rowL0 = rowL0 * fac0 + sum0;
    rowL1 = rowL1 * fac1 + sum1;
#pragma unroll
    for (int nf = 0; nf < 8; nf++) {
      accO[nf][0] *= fac0; accO[nf][1] *= fac0;
      accO[nf][2] *= fac1; accO[nf][3] *= fac1;
    }

    // --- store P (A-frag, fp16, warp-private mf = w) ---
#pragma unroll
    for (int nf = 0; nf < 8; nf++) {
      const int word = ((nf >> 1) * 8 + w) * 128 + lane * 4 + (nf & 1) * 2;
      Ps[word + 0] = pack_h2(accS[nf][0], accS[nf][1]);
      Ps[word + 1] = pack_h2(accS[nf][2], accS[nf][3]);
    }
    __syncwarp();

    // --- O += P V ---
#pragma unroll
    for (int kcP = 0; kcP < 4; kcP++) {
      uint32_t aP[4];
      const uint4 v = *(const uint4*)&Ps[(kcP * 8 + w) * 128 + lane * 4];
      aP[0] = v.x; aP[1] = v.y; aP[2] = v.z; aP[3] = v.w;
#pragma unroll
      for (int nf = 0; nf < 8; nf++) {
        uint32_t bf[2];
        const uint32_t* p = &Vs[(kcP * 8 + nf) * 64 + lane * 2];
        bf[0] = p[0]; bf[1] = p[1];
        mma_f16(accO[nf], aP, bf);
      }
    }
    __syncwarp();
  }

  // --- epilogue: normalize + write g_att16[B,N,C] ---
  const float inv0 = 1.f / rowL0, inv1 = 1.f / rowL1;
  const int row0 = q0 + w * 16 + g;
#pragma unroll
  for (int nf = 0; nf < 8; nf++) {
    const int col = h * 64 + nf * 8 + t * 2;
    const size_t i0 = (size_t)(b * N_ + row0) * C_ + col;
    const size_t i1 = (size_t)(b * N_ + row0 + 8) * C_ + col;
    ((uint32_t*)g_att16)[i0 >> 1] = pack_h2(accO[nf][0] * inv0, accO[nf][1] * inv0);
    ((uint32_t*)g_att16)[i1 >> 1] = pack_h2(accO[nf][2] * inv1, accO[nf][3] * inv1);
  }
}

extern "C" void kernel_launch(void* const* d_in, const int* in_sizes, int n_in,
                              void* d_out, int out_size) {
  const float* x      = (const float*)d_in[0];
  const int*   pad    = (const int*)  d_in[1];
  const float* w_attn = (const float*)d_in[2];
  const float* b_attn = (const float*)d_in[3];
  const float* w_proj = (const float*)d_in[4];
  const float* b_proj = (const float*)d_in[5];
  float* out = (float*)d_out;

  // 0) prep: fp16 conversions / weight transposes
  cvt_x_kernel<<<(M_*C_/4 + 255) / 256, 256>>>(x);
  transpose_h_kernel<true> <<<dim3(2304/32, 768/32), dim3(32, 8)>>>(w_attn, 2304);
  transpose_h_kernel<false><<<dim3(768/32,  768/32), dim3(32, 8)>>>(w_proj, 768);
  // 1) QKV projection (fp16 mma) + bias -> fp16 [B,H,N,D]
  mma_gemm<true><<<dim3(18, 64), 256>>>(b_attn, nullptr);
  // 2) fused attention (fp16 mma flash attention) -> fp16 [B,N,C]
  attn_mma<<<dim3(8, 96), 256>>>(pad);
  // 3) output projection (fp16 mma) + bias -> fp32 d_out
  mma_gemm<false><<<dim3(6, 64), 256>>>(b_proj, out);
}

// round 12
// speedup vs baseline: 3.3657x; 1.1163x over previous
#include <cuda_runtime.h>
#include <cuda_fp16.h>
#include <math.h>
#include <stdint.h>

#define B_ 8
#define N_ 1024
#define C_ 768
#define H_ 12
#define D_ 64
#define M_ (B_*N_)   // 8192

// Scratch (allocation-free rule: __device__ globals), fp16 operands
__device__ __align__(16) __half g_x16[M_*C_];        // x, row-major [m][768]
__device__ __align__(16) __half g_wa16[3*C_*C_];     // w_attn^T [2304][768]
__device__ __align__(16) __half g_wp16[C_*C_];       // w_proj^T [768][768]
__device__ __align__(16) __half g_q16[B_*H_*N_*D_];  // [B,H,N,D]
__device__ __align__(16) __half g_k16[B_*H_*N_*D_];
__device__ __align__(16) __half g_v16[B_*H_*N_*D_];
__device__ __align__(16) __half g_att16[M_*C_];      // [B,N,C]

__device__ __forceinline__ uint32_t pack_h2(float x, float y) {
  __half2 h = __floats2half2_rn(x, y);
  return *reinterpret_cast<uint32_t*>(&h);
}

__device__ __forceinline__ void mma_f16(float* d, const uint32_t* a, const uint32_t* b) {
  asm volatile(
    "mma.sync.aligned.m16n8k16.row.col.f32.f16.f16.f32 "
    "{%0,%1,%2,%3}, {%4,%5,%6,%7}, {%8,%9}, {%0,%1,%2,%3};"
    : "+f"(d[0]), "+f"(d[1]), "+f"(d[2]), "+f"(d[3])
    : "r"(a[0]), "r"(a[1]), "r"(a[2]), "r"(a[3]), "r"(b[0]), "r"(b[1]));
}

__device__ __forceinline__ void ldsm4(uint32_t* r, uint32_t a) {
  asm volatile("ldmatrix.sync.aligned.m8n8.x4.shared.b16 {%0,%1,%2,%3}, [%4];"
    : "=r"(r[0]), "=r"(r[1]), "=r"(r[2]), "=r"(r[3]) : "r"(a));
}
__device__ __forceinline__ void ldsm4t(uint32_t* r, uint32_t a) {
  asm volatile("ldmatrix.sync.aligned.m8n8.x4.trans.shared.b16 {%0,%1,%2,%3}, [%4];"
    : "=r"(r[0]), "=r"(r[1]), "=r"(r[2]), "=r"(r[3]) : "r"(a));
}
__device__ __forceinline__ uint32_t smaddr(const void* p) {
  return (uint32_t)__cvta_generic_to_shared(p);
}

// ---------------------------------------------------------------------------
// Prep kernels: fp32 -> fp16 convert / transpose (run once per launch)
// ---------------------------------------------------------------------------
__global__ void cvt_x_kernel(const float* __restrict__ x) {
  const int i = blockIdx.x * 256 + threadIdx.x;
  const float4 v = ((const float4*)x)[i];
  uint2 o;
  o.x = pack_h2(v.x, v.y);
  o.y = pack_h2(v.z, v.w);
  ((uint2*)g_x16)[i] = o;
}

template<bool ATTN>   // src [768(k)][cols(n)] -> dst fp16 [n][k]
__global__ void transpose_h_kernel(const float* __restrict__ src, int cols) {
  __shared__ float tb[32][33];
  __half* dst = ATTN ? g_wa16 : g_wp16;
  const int cb = blockIdx.x * 32, rb = blockIdx.y * 32;
  const int x = threadIdx.x, y = threadIdx.y;
#pragma unroll
  for (int i = 0; i < 32; i += 8)
    tb[y + i][x] = src[(size_t)(rb + y + i) * cols + cb + x];
  __syncthreads();
#pragma unroll
  for (int i = 0; i < 32; i += 8)
    dst[(size_t)(cb + y + i) * 768 + rb + x] = __float2half_rn(tb[x][y + i]);
}

// ---------------------------------------------------------------------------
// fp16 tensor-core GEMM via ldmatrix: Out[m][n] = sum_k A[m][k]*W[n][k] (+bias)
// CTA 128x128, 8 warps (4m x 2n), K=16/stage, double-buffered.
// Smem row-major, pitch 24 halves (16 data + 8 pad): rows 0..7 hit distinct
// bank groups -> STS.128 staging AND all ldmatrix loads conflict-free.
// ---------------------------------------------------------------------------
#define GP 24   // GEMM smem pitch (halves)
template<bool QKV>
__global__ __launch_bounds__(256, 2) void mma_gemm(
    const float* __restrict__ bias, float* __restrict__ Out)
{
  __shared__ __half Asm[2][128 * GP];   // 12KB
  __shared__ __half Bsm[2][128 * GP];   // 12KB

  const int tid  = threadIdx.x;
  const int lane = tid & 31;
  const int w    = tid >> 5;
  const int wm   = w & 3;
  const int wn   = w >> 2;
  const int m0 = blockIdx.y * 128, n0 = blockIdx.x * 128;

  const __half* A16 = QKV ? g_x16 : g_att16;
  const __half* W16 = QKV ? g_wa16 : g_wp16;

  float acc[2][8][4];
#pragma unroll
  for (int i = 0; i < 2; i++)
#pragma unroll
    for (int j = 0; j < 8; j++)
#pragma unroll
      for (int q = 0; q < 4; q++) acc[i][j][q] = 0.f;

  // staging: r = tid&127 (row), k8 = tid>>7 (which 8-half chunk)
  const int s_r = tid & 127, s_k8 = tid >> 7;
  const __half* aptr = A16 + (size_t)(m0 + s_r) * 768 + s_k8 * 8;
  const __half* bptr = W16 + (size_t)(n0 + s_r) * 768 + s_k8 * 8;
  __half* a_st = &Asm[0][s_r * GP + s_k8 * 8];
  __half* b_st = &Bsm[0][s_r * GP + s_k8 * 8];

  uint4 pa, pb;
  auto load_stage = [&](int kt) {
    pa = *(const uint4*)(aptr + kt * 16);
    pb = *(const uint4*)(bptr + kt * 16);
  };
  auto store_stage = [&](int buf) {
    *(uint4*)(a_st + buf * 128 * GP) = pa;
    *(uint4*)(b_st + buf * 128 * GP) = pb;
  };

  // ldmatrix lane addressing
  const int lrow = (lane & 7) + ((lane >> 3) & 1) * 8;   // row within 16-frag
  const int lkc  = (lane >> 4) * 8;                      // k-chunk (halves)
  uint32_t aAddr[2], bAddr[4];
#pragma unroll
  for (int mf2 = 0; mf2 < 2; mf2++)
    aAddr[mf2] = smaddr(&Asm[0][(wm * 32 + mf2 * 16 + lrow) * GP + lkc]);
  // B tiles: lanes 0-7: nf_e k0 | 8-15: nf_e k8 | 16-23: nf_o k0 | 24-31: nf_o k8
  const int brow = 8 * (lane >> 4) + (lane & 7);
  const int bkc  = ((lane >> 3) & 1) * 8;
#pragma unroll
  for (int p = 0; p < 4; p++)
    bAddr[p] = smaddr(&Bsm[0][(wn * 64 + p * 16 + brow) * GP + bkc]);
  const uint32_t bufoff = 128 * GP * 2;   // bytes between buffers

  load_stage(0);
  store_stage(0);
  load_stage(1);
  __syncthreads();

  for (int kt = 0; kt < 48; kt++) {
    const int cur = kt & 1, nxt = cur ^ 1;
    if (kt < 47) store_stage(nxt);
    if (kt < 46) load_stage(kt + 2);

    uint32_t af[2][4];
    ldsm4(af[0], aAddr[0] + cur * bufoff);
    ldsm4(af[1], aAddr[1] + cur * bufoff);
#pragma unroll
    for (int p = 0; p < 4; p++) {
      uint32_t bf[4];   // {b0_e, b1_e, b0_o, b1_o}
      ldsm4(bf, bAddr[p] + cur * bufoff);
      mma_f16(acc[0][2 * p + 0], af[0], bf + 0);
      mma_f16(acc[0][2 * p + 1], af[0], bf + 2);
      mma_f16(acc[1][2 * p + 0], af[1], bf + 0);
      mma_f16(acc[1][2 * p + 1], af[1], bf + 2);
    }
    __syncthreads();
  }

  // --- epilogue ---
  const int g = lane >> 2, tq = lane & 3;
#pragma unroll
  for (int mf2 = 0; mf2 < 2; mf2++) {
    const int r0 = m0 + wm * 32 + mf2 * 16 + g;
#pragma unroll
    for (int nf = 0; nf < 8; nf++) {
      const int col = n0 + wn * 64 + nf * 8 + tq * 2;
      const float bx = bias[col], by = bias[col + 1];
#pragma unroll
      for (int half_ = 0; half_ < 2; half_++) {
        const int r = r0 + half_ * 8;
        const float ox = acc[mf2][nf][half_ * 2 + 0] + bx;
        const float oy = acc[mf2][nf][half_ * 2 + 1] + by;
        if (QKV) {
          const int bb = r >> 10, t = r & 1023;
          const int which = col / 768;
          const int c = col - which * 768;
          const int hh = c >> 6, d = c & 63;
          __half* dst = (which == 0) ? g_q16 : (which == 1) ? g_k16 : g_v16;
          const size_t idx = ((size_t)((bb * 12 + hh) * 1024 + t)) * 64 + d;
          ((uint32_t*)dst)[idx >> 1] = pack_h2(ox, oy);
        } else {
          float2 o; o.x = ox; o.y = oy;
          *(float2*)&Out[(size_t)r * 768 + col] = o;
        }
      }
    }
  }
}

// ---------------------------------------------------------------------------
// fp16 flash attention via ldmatrix.
// CTA: 128 Q-rows of one (b,h); 8 warps; warp w owns rows [16w,16w+16).
// Smem (36KB static), row-major pitch 72 halves (64 data + 8 pad):
//   sQ[128][72] (warp w's 16 rows become its private P buffer after hoist)
//   sK[64][72] | sV[64][72]
// Q/K/P frags: ldmatrix.x4; V frags: ldmatrix.x4.trans. All conflict-free.
// ---------------------------------------------------------------------------
#define AP 72   // attention smem pitch (halves)
__global__ __launch_bounds__(256) void attn_mma(const int* __restrict__ pad_mask)
{
  __shared__ __half sQ[128 * AP];   // 18KB (P aliases per-warp rows)
  __shared__ __half sK[64 * AP];    // 9KB
  __shared__ __half sV[64 * AP];    // 9KB

  const int tid  = threadIdx.x;
  const int lane = tid & 31;
  const int w    = tid >> 5;
  const int g    = lane >> 2;
  const int t    = lane & 3;
  const int bh = blockIdx.y;
  const int b  = bh / 12, h = bh % 12;
  const int q0 = blockIdx.x << 7;

  const __half* Qg = g_q16 + (size_t)bh * (N_*D_) + (size_t)q0 * D_;
  const __half* Kg = g_k16 + (size_t)bh * (N_*D_);
  const __half* Vg = g_v16 + (size_t)bh * (N_*D_);

  // --- stage Q row-major (conflict-free STS.128) ---
#pragma unroll
  for (int it = 0; it < 4; it++) {
    const int idx = tid + it * 256;        // 0..1023
    const int r = idx >> 3, d8 = idx & 7;
    *(uint4*)&sQ[r * AP + d8 * 8] = *(const uint4*)(Qg + (size_t)r * 64 + d8 * 8);
  }
  __syncthreads();

  // --- hoist Q fragments (warp-private rows 16w..16w+15) ---
  const int lrow = (lane & 7) + ((lane >> 3) & 1) * 8;
  const uint32_t qAddr = smaddr(&sQ[(w * 16 + lrow) * AP + (lane >> 4) * 8]);
  uint32_t aQ[4][4];
#pragma unroll
  for (int kc = 0; kc < 4; kc++)
    ldsm4(aQ[kc], qAddr + kc * 32);        // +16 halves per kc

  // K frag addresses (B-frag, non-trans): rows = keys, k = d
  const int brow = 8 * (lane >> 4) + (lane & 7);
  const int bkc  = ((lane >> 3) & 1) * 8;
  uint32_t kAddr[4], vAddr[4];
#pragma unroll
  for (int p = 0; p < 4; p++) {
    kAddr[p] = smaddr(&sK[(p * 16 + brow) * AP + bkc]);
    // V (trans): lanes 0-7 keys+0 d0 | 8-15 keys+8 d0 | 16-23 keys+0 d8 | 24-31 keys+8 d8
    vAddr[p] = smaddr(&sV[(8 * ((lane >> 3) & 1) + (lane & 7)) * AP + p * 16 + (lane >> 4) * 8]);
  }
  __half* Pw = &sQ[w * 16 * AP];           // warp-private P (aliases own Q rows)
  const uint32_t pAddr = smaddr(&Pw[lrow * AP + (lane >> 4) * 8]);

  const bool mz0 = (pad_mask[b * N_ + q0 + w * 16 + g] == 0);
  const bool mz1 = (pad_mask[b * N_ + q0 + w * 16 + g + 8] == 0);

  float accO[8][4];
#pragma unroll
  for (int nf = 0; nf < 8; nf++)
#pragma unroll
    for (int j = 0; j < 4; j++) accO[nf][j] = 0.f;
  float rowM0 = -INFINITY, rowM1 = -INFINITY, rowL0 = 0.f, rowL1 = 0.f;

  for (int kt = 0; kt < 16; kt++) {
    __syncthreads();
    // --- stage K, V row-major (conflict-free) ---
#pragma unroll
    for (int it = 0; it < 2; it++) {
      const int idx = tid + it * 256;      // 0..511
      const int r = idx >> 3, d8 = idx & 7;
      *(uint4*)&sK[r * AP + d8 * 8] = *(const uint4*)(Kg + (size_t)(kt * 64 + r) * 64 + d8 * 8);
      *(uint4*)&sV[r * AP + d8 * 8] = *(const uint4*)(Vg + (size_t)(kt * 64 + r) * 64 + d8 * 8);
    }
    __syncthreads();

    // --- S = Q K^T ---
    float accS[8][4];
#pragma unroll
    for (int nf = 0; nf < 8; nf++)
#pragma unroll
      for (int j = 0; j < 4; j++) accS[nf][j] = 0.f;
#pragma unroll
    for (int kc = 0; kc < 4; kc++) {
#pragma unroll
      for (int p = 0; p < 4; p++) {
        uint32_t bf[4];
        ldsm4(bf, kAddr[p] + kc * 32);
        mma_f16(accS[2 * p + 0], aQ[kc], bf + 0);
        mma_f16(accS[2 * p + 1], aQ[kc], bf + 2);
      }
    }

    // --- online softmax (warp-local; rows g and g+8) ---
    float mx0 = -INFINITY, mx1 = -INFINITY;
#pragma unroll
    for (int nf = 0; nf < 8; nf++) {
      accS[nf][0] = mz0 ? -INFINITY : accS[nf][0] * 0.125f;
      accS[nf][1] = mz0 ? -INFINITY : accS[nf][1] * 0.125f;
      accS[nf][2] = mz1 ? -INFINITY : accS[nf][2] * 0.125f;
      accS[nf][3] = mz1 ? -INFINITY : accS[nf][3] * 0.125f;
      mx0 = fmaxf(mx0, fmaxf(accS[nf][0], accS[nf][1]));
      mx1 = fmaxf(mx1, fmaxf(accS[nf][2], accS[nf][3]));
    }
#pragma unroll
    for (int o = 1; o <= 2; o <<= 1) {
      mx0 = fmaxf(mx0, __shfl_xor_sync(0xffffffffu, mx0, o));
      mx1 = fmaxf(mx1, __shfl_xor_sync(0xffffffffu, mx1, o));
    }
    const float mn0 = fmaxf(rowM0, mx0), mn1 = fmaxf(rowM1, mx1);
    const float fac0 = __expf(rowM0 - mn0), fac1 = __expf(rowM1 - mn1);
    rowM0 = mn0; rowM1 = mn1;
    float sum0 = 0.f, sum1 = 0.f;
#pragma unroll
    for (int nf = 0; nf < 8; nf++) {
      accS[nf][0] = __expf(accS[nf][0] - mn0);
      accS[nf][1] = __expf(accS[nf][1] - mn0);
      accS[nf][2] = __expf(accS[nf][2] - mn1);
      accS[nf][3] = __expf(accS[nf][3] - mn1);
      sum0 += accS[nf][0] + accS[nf][1];
      sum1 += accS[nf][2] + accS[nf][3];
    }
#pragma unroll
    for (int o = 1; o <= 2; o <<= 1) {
      sum0 += __shfl_xor_sync(0xffffffffu, sum0, o);
      sum1 += __shfl_xor_sync(0xffffffffu, sum1, o);
    }
    rowL0 = rowL0 * fac0 + sum0;
    rowL1 = rowL1 * fac1 + sum1;
#pragma unroll
    for (int nf = 0; nf < 8; nf++) {
      accO[nf][0] *= fac0; accO[nf][1] *= fac0;
      accO[nf][2] *= fac1; accO[nf][3] *= fac1;
    }

    // --- store P row-major (banks 4g+t: conflict-free) ---
#pragma unroll
    for (int nf = 0; nf < 8; nf++) {
      *(uint32_t*)&Pw[g * AP + nf * 8 + 2 * t]       = pack_h2(accS[nf][0], accS[nf][1]);
      *(uint32_t*)&Pw[(g + 8) * AP + nf * 8 + 2 * t] = pack_h2(accS[nf][2], accS[nf][3]);
    }
    __syncwarp();

    // --- O += P V ---
#pragma unroll
    for (int kcP = 0; kcP < 4; kcP++) {
      uint32_t aP[4];
      ldsm4(aP, pAddr + kcP * 32);
#pragma unroll
      for (int p = 0; p < 4; p++) {
        uint32_t bf[4];
        ldsm4t(bf, vAddr[p] + kcP * (16 * AP * 2));   // +16 key rows
        mma_f16(accO[2 * p + 0], aP, bf + 0);
        mma_f16(accO[2 * p + 1], aP, bf + 2);
      }
    }
    __syncwarp();
  }

  // --- epilogue: normalize + write g_att16[B,N,C] ---
  const float inv0 = 1.f / rowL0, inv1 = 1.f / rowL1;
  const int row0 = q0 + w * 16 + g;
#pragma unroll
  for (int nf = 0; nf < 8; nf++) {
    const int col = h * 64 + nf * 8 + t * 2;
    const size_t i0 = (size_t)(b * N_ + row0) * C_ + col;
    const size_t i1 = (size_t)(b * N_ + row0 + 8) * C_ + col;
    ((uint32_t*)g_att16)[i0 >> 1] = pack_h2(accO[nf][0] * inv0, accO[nf][1] * inv0);
    ((uint32_t*)g_att16)[i1 >> 1] = pack_h2(accO[nf][2] * inv1, accO[nf][3] * inv1);
  }
}

extern "C" void kernel_launch(void* const* d_in, const int* in_sizes, int n_in,
                              void* d_out, int out_size) {
  const float* x      = (const float*)d_in[0];
  const int*   pad    = (const int*)  d_in[1];
  const float* w_attn = (const float*)d_in[2];
  const float* b_attn = (const float*)d_in[3];
  const float* w_proj = (const float*)d_in[4];
  const float* b_proj = (const float*)d_in[5];
  float* out = (float*)d_out;

  // 0) prep: fp16 conversions / weight transposes
  cvt_x_kernel<<<(M_*C_/4 + 255) / 256, 256>>>(x);
  transpose_h_kernel<true> <<<dim3(2304/32, 768/32), dim3(32, 8)>>>(w_attn, 2304);
  transpose_h_kernel<false><<<dim3(768/32,  768/32), dim3(32, 8)>>>(w_proj, 768);
  // 1) QKV projection -> fp16 [B,H,N,D]
  mma_gemm<true><<<dim3(18, 64), 256>>>(b_attn, nullptr);
  // 2) fused attention -> fp16 [B,N,C]
  attn_mma<<<dim3(8, 96), 256>>>(pad);
  // 3) output projection -> fp32 d_out
  mma_gemm<false><<<dim3(6, 64), 256>>>(b_proj, out);
}

// round 14
// speedup vs baseline: 3.7586x; 1.1167x over previous
#include <cuda_runtime.h>
#include <cuda_fp16.h>
#include <math.h>
#include <stdint.h>

#define B_ 8
#define N_ 1024
#define C_ 768
#define H_ 12
#define D_ 64
#define M_ (B_*N_)   // 8192

// Scratch (allocation-free rule: __device__ globals), fp16 operands
__device__ __align__(16) __half g_x16[M_*C_];        // x, row-major [m][768]
__device__ __align__(16) __half g_wa16[3*C_*C_];     // w_attn^T [2304][768]
__device__ __align__(16) __half g_wp16[C_*C_];       // w_proj^T [768][768]
__device__ __align__(16) __half g_q16[B_*H_*N_*D_];  // [B,H,N,D]
__device__ __align__(16) __half g_k16[B_*H_*N_*D_];
__device__ __align__(16) __half g_v16[B_*H_*N_*D_];
__device__ __align__(16) __half g_att16[M_*C_];      // [B,N,C]

__device__ __forceinline__ uint32_t pack_h2(float x, float y) {
  __half2 h = __floats2half2_rn(x, y);
  return *reinterpret_cast<uint32_t*>(&h);
}

__device__ __forceinline__ void mma_f16(float* d, const uint32_t* a, const uint32_t* b) {
  asm volatile(
    "mma.sync.aligned.m16n8k16.row.col.f32.f16.f16.f32 "
    "{%0,%1,%2,%3}, {%4,%5,%6,%7}, {%8,%9}, {%0,%1,%2,%3};"
    : "+f"(d[0]), "+f"(d[1]), "+f"(d[2]), "+f"(d[3])
    : "r"(a[0]), "r"(a[1]), "r"(a[2]), "r"(a[3]), "r"(b[0]), "r"(b[1]));
}

__device__ __forceinline__ void ldsm4(uint32_t* r, uint32_t a) {
  asm volatile("ldmatrix.sync.aligned.m8n8.x4.shared.b16 {%0,%1,%2,%3}, [%4];"
    : "=r"(r[0]), "=r"(r[1]), "=r"(r[2]), "=r"(r[3]) : "r"(a));
}
__device__ __forceinline__ void ldsm4t(uint32_t* r, uint32_t a) {
  asm volatile("ldmatrix.sync.aligned.m8n8.x4.trans.shared.b16 {%0,%1,%2,%3}, [%4];"
    : "=r"(r[0]), "=r"(r[1]), "=r"(r[2]), "=r"(r[3]) : "r"(a));
}
__device__ __forceinline__ uint32_t smaddr(const void* p) {
  return (uint32_t)__cvta_generic_to_shared(p);
}

// ---------------------------------------------------------------------------
// Prep kernels
// ---------------------------------------------------------------------------
__global__ void cvt_x_kernel(const float* __restrict__ x) {
  const int i = blockIdx.x * 256 + threadIdx.x;
  const float4 v = ((const float4*)x)[i];
  uint2 o;
  o.x = pack_h2(v.x, v.y);
  o.y = pack_h2(v.z, v.w);
  ((uint2*)g_x16)[i] = o;
}

template<bool ATTN>   // src [768(k)][cols(n)] -> dst fp16 [n][k]
__global__ void transpose_h_kernel(const float* __restrict__ src, int cols) {
  __shared__ float tb[32][33];
  __half* dst = ATTN ? g_wa16 : g_wp16;
  const int cb = blockIdx.x * 32, rb = blockIdx.y * 32;
  const int x = threadIdx.x, y = threadIdx.y;
#pragma unroll
  for (int i = 0; i < 32; i += 8)
    tb[y + i][x] = src[(size_t)(rb + y + i) * cols + cb + x];
  __syncthreads();
#pragma unroll
  for (int i = 0; i < 32; i += 8)
    dst[(size_t)(cb + y + i) * 768 + rb + x] = __float2half_rn(tb[x][y + i]);
}

// ---------------------------------------------------------------------------
// fp16 GEMM, 64x64 warp tiles for fragment reuse (128 B LDS per mma).
// CTA tile 256m x 128n, 8 warps (4m x 2n), K=16/stage, double-buffered.
// Smem row-major pitch 24 halves (conflict-free STS.128 + ldmatrix).
// ---------------------------------------------------------------------------
#define GP 24
template<bool QKV>
__global__ __launch_bounds__(256) void mma_gemm(
    const float* __restrict__ bias, float* __restrict__ Out)
{
  __shared__ __half Asm[2][256 * GP];   // 24KB
  __shared__ __half Bsm[2][128 * GP];   // 12KB

  const int tid  = threadIdx.x;
  const int lane = tid & 31;
  const int w    = tid >> 5;
  const int wm   = w >> 1;           // 0..3  (64-row stripe)
  const int wn   = w & 1;            // 0..1  (64-col stripe)
  const int m0 = blockIdx.y * 256, n0 = blockIdx.x * 128;

  const __half* A16 = QKV ? g_x16 : g_att16;
  const __half* W16 = QKV ? g_wa16 : g_wp16;

  float acc[4][8][4];
#pragma unroll
  for (int i = 0; i < 4; i++)
#pragma unroll
    for (int j = 0; j < 8; j++)
#pragma unroll
      for (int q = 0; q < 4; q++) acc[i][j][q] = 0.f;

  // staging: A row = tid (2 chunks), B row = tid&127, chunk tid>>7
  const int b_r = tid & 127, b_k8 = tid >> 7;
  const __half* aptr = A16 + (size_t)(m0 + tid) * 768;
  const __half* bptr = W16 + (size_t)(n0 + b_r) * 768 + b_k8 * 8;
  __half* a_st = &Asm[0][tid * GP];
  __half* b_st = &Bsm[0][b_r * GP + b_k8 * 8];

  uint4 pa0, pa1, pb;
  auto load_stage = [&](int kt) {
    pa0 = *(const uint4*)(aptr + kt * 16);
    pa1 = *(const uint4*)(aptr + kt * 16 + 8);
    pb  = *(const uint4*)(bptr + kt * 16);
  };
  auto store_stage = [&](int buf) {
    *(uint4*)(a_st + buf * 256 * GP + 0) = pa0;
    *(uint4*)(a_st + buf * 256 * GP + 8) = pa1;
    *(uint4*)(b_st + buf * 128 * GP)     = pb;
  };

  // ldmatrix lane addressing
  const int lrow = (lane & 7) + ((lane >> 3) & 1) * 8;
  const int lkc  = (lane >> 4) * 8;
  uint32_t aAddr[4], bAddr[4];
#pragma unroll
  for (int mf = 0; mf < 4; mf++)
    aAddr[mf] = smaddr(&Asm[0][(wm * 64 + mf * 16 + lrow) * GP + lkc]);
  const int brow = 8 * (lane >> 4) + (lane & 7);
  const int bkc  = ((lane >> 3) & 1) * 8;
#pragma unroll
  for (int p = 0; p < 4; p++)
    bAddr[p] = smaddr(&Bsm[0][(wn * 64 + p * 16 + brow) * GP + bkc]);
  const uint32_t aBuf = 256 * GP * 2;   // bytes between A buffers
  const uint32_t bBuf = 128 * GP * 2;

  load_stage(0);
  store_stage(0);
  load_stage(1);
  __syncthreads();

  for (int kt = 0; kt < 48; kt++) {
    const int cur = kt & 1, nxt = cur ^ 1;
    if (kt < 47) store_stage(nxt);
    if (kt < 46) load_stage(kt + 2);

    uint32_t af[4][4];
#pragma unroll
    for (int mf = 0; mf < 4; mf++)
      ldsm4(af[mf], aAddr[mf] + cur * aBuf);
#pragma unroll
    for (int p = 0; p < 4; p++) {
      uint32_t bf[4];   // {b0_e, b1_e, b0_o, b1_o}
      ldsm4(bf, bAddr[p] + cur * bBuf);
#pragma unroll
      for (int mf = 0; mf < 4; mf++) {
        mma_f16(acc[mf][2 * p + 0], af[mf], bf + 0);
        mma_f16(acc[mf][2 * p + 1], af[mf], bf + 2);
      }
    }
    __syncthreads();
  }

  // --- epilogue ---
  const int g = lane >> 2, tq = lane & 3;
#pragma unroll
  for (int mf = 0; mf < 4; mf++) {
    const int r0 = m0 + wm * 64 + mf * 16 + g;
#pragma unroll
    for (int nf = 0; nf < 8; nf++) {
      const int col = n0 + wn * 64 + nf * 8 + tq * 2;
      const float bx = bias[col], by = bias[col + 1];
#pragma unroll
      for (int half_ = 0; half_ < 2; half_++) {
        const int r = r0 + half_ * 8;
        const float ox = acc[mf][nf][half_ * 2 + 0] + bx;
        const float oy = acc[mf][nf][half_ * 2 + 1] + by;
        if (QKV) {
          const int bb = r >> 10, t = r & 1023;
          const int which = col / 768;
          const int c = col - which * 768;
          const int hh = c >> 6, d = c & 63;
          __half* dst = (which == 0) ? g_q16 : (which == 1) ? g_k16 : g_v16;
          const size_t idx = ((size_t)((bb * 12 + hh) * 1024 + t)) * 64 + d;
          ((uint32_t*)dst)[idx >> 1] = pack_h2(ox, oy);
        } else {
          float2 o; o.x = ox; o.y = oy;
          *(float2*)&Out[(size_t)r * 768 + col] = o;
        }
      }
    }
  }
}

// ---------------------------------------------------------------------------
// fp16 flash attention via ldmatrix (unchanged from R12 — proven).
// ---------------------------------------------------------------------------
#define AP 72
__global__ __launch_bounds__(256) void attn_mma(const int* __restrict__ pad_mask)
{
  __shared__ __half sQ[128 * AP];   // 18KB (P aliases per-warp rows)
  __shared__ __half sK[64 * AP];    // 9KB
  __shared__ __half sV[64 * AP];    // 9KB

  const int tid  = threadIdx.x;
  const int lane = tid & 31;
  const int w    = tid >> 5;
  const int g    = lane >> 2;
  const int t    = lane & 3;
  const int bh = blockIdx.y;
  const int b  = bh / 12, h = bh % 12;
  const int q0 = blockIdx.x << 7;

  const __half* Qg = g_q16 + (size_t)bh * (N_*D_) + (size_t)q0 * D_;
  const __half* Kg = g_k16 + (size_t)bh * (N_*D_);
  const __half* Vg = g_v16 + (size_t)bh * (N_*D_);

#pragma unroll
  for (int it = 0; it < 4; it++) {
    const int idx = tid + it * 256;
    const int r = idx >> 3, d8 = idx & 7;
    *(uint4*)&sQ[r * AP + d8 * 8] = *(const uint4*)(Qg + (size_t)r * 64 + d8 * 8);
  }
  __syncthreads();

  const int lrow = (lane & 7) + ((lane >> 3) & 1) * 8;
  const uint32_t qAddr = smaddr(&sQ[(w * 16 + lrow) * AP + (lane >> 4) * 8]);
  uint32_t aQ[4][4];
#pragma unroll
  for (int kc = 0; kc < 4; kc++)
    ldsm4(aQ[kc], qAddr + kc * 32);

  const int brow = 8 * (lane >> 4) + (lane & 7);
  const int bkc  = ((lane >> 3) & 1) * 8;
  uint32_t kAddr[4], vAddr[4];
#pragma unroll
  for (int p = 0; p < 4; p++) {
    kAddr[p] = smaddr(&sK[(p * 16 + brow) * AP + bkc]);
    vAddr[p] = smaddr(&sV[(8 * ((lane >> 3) & 1) + (lane & 7)) * AP + p * 16 + (lane >> 4) * 8]);
  }
  __half* Pw = &sQ[w * 16 * AP];
  const uint32_t pAddr = smaddr(&Pw[lrow * AP + (lane >> 4) * 8]);

  const bool mz0 = (pad_mask[b * N_ + q0 + w * 16 + g] == 0);
  const bool mz1 = (pad_mask[b * N_ + q0 + w * 16 + g + 8] == 0);

  float accO[8][4];
#pragma unroll
  for (int nf = 0; nf < 8; nf++)
#pragma unroll
    for (int j = 0; j < 4; j++) accO[nf][j] = 0.f;
  float rowM0 = -INFINITY, rowM1 = -INFINITY, rowL0 = 0.f, rowL1 = 0.f;

  for (int kt = 0; kt < 16; kt++) {
    __syncthreads();
#pragma unroll
    for (int it = 0; it < 2; it++) {
      const int idx = tid + it * 256;
      const int r = idx >> 3, d8 = idx & 7;
      *(uint4*)&sK[r * AP + d8 * 8] = *(const uint4*)(Kg + (size_t)(kt * 64 + r) * 64 + d8 * 8);
      *(uint4*)&sV[r * AP + d8 * 8] = *(const uint4*)(Vg + (size_t)(kt * 64 + r) * 64 + d8 * 8);
    }
    __syncthreads();

    float accS[8][4];
#pragma unroll
    for (int nf = 0; nf < 8; nf++)
#pragma unroll
      for (int j = 0; j < 4; j++) accS[nf][j] = 0.f;
#pragma unroll
    for (int kc = 0; kc < 4; kc++) {
#pragma unroll
      for (int p = 0; p < 4; p++) {
        uint32_t bf[4];
        ldsm4(bf, kAddr[p] + kc * 32);
        mma_f16(accS[2 * p + 0], aQ[kc], bf + 0);
        mma_f16(accS[2 * p + 1], aQ[kc], bf + 2);
      }
    }

    float mx0 = -INFINITY, mx1 = -INFINITY;
#pragma unroll
    for (int nf = 0; nf < 8; nf++) {
      accS[nf][0] = mz0 ? -INFINITY : accS[nf][0] * 0.125f;
      accS[nf][1] = mz0 ? -INFINITY : accS[nf][1] * 0.125f;
      accS[nf][2] = mz1 ? -INFINITY : accS[nf][2] * 0.125f;
      accS[nf][3] = mz1 ? -INFINITY : accS[nf][3] * 0.125f;
      mx0 = fmaxf(mx0, fmaxf(accS[nf][0], accS[nf][1]));
      mx1 = fmaxf(mx1, fmaxf(accS[nf][2], accS[nf][3]));
    }
#pragma unroll
    for (int o = 1; o <= 2; o <<= 1) {
      mx0 = fmaxf(mx0, __shfl_xor_sync(0xffffffffu, mx0, o));
      mx1 = fmaxf(mx1, __shfl_xor_sync(0xffffffffu, mx1, o));
    }
    const float mn0 = fmaxf(rowM0, mx0), mn1 = fmaxf(rowM1, mx1);
    const float fac0 = __expf(rowM0 - mn0), fac1 = __expf(rowM1 - mn1);
    rowM0 = mn0; rowM1 = mn1;
    float sum0 = 0.f, sum1 = 0.f;
#pragma unroll
    for (int nf = 0; nf < 8; nf++) {
      accS[nf][0] = __expf(accS[nf][0] - mn0);
      accS[nf][1] = __expf(accS[nf][1] - mn0);
      accS[nf][2] = __expf(accS[nf][2] - mn1);
      accS[nf][3] = __expf(accS[nf][3] - mn1);
      sum0 += accS[nf][0] + accS[nf][1];
      sum1 += accS[nf][2] + accS[nf][3];
    }
#pragma unroll
    for (int o = 1; o <= 2; o <<= 1) {
      sum0 += __shfl_xor_sync(0xffffffffu, sum0, o);
      sum1 += __shfl_xor_sync(0xffffffffu, sum1, o);
    }
    rowL0 = rowL0 * fac0 + sum0;
    rowL1 = rowL1 * fac1 + sum1;
#pragma unroll
    for (int nf = 0; nf < 8; nf++) {
      accO[nf][0] *= fac0; accO[nf][1] *= fac0;
      accO[nf][2] *= fac1; accO[nf][3] *= fac1;
    }

#pragma unroll
    for (int nf = 0; nf < 8; nf++) {
      *(uint32_t*)&Pw[g * AP + nf * 8 + 2 * t]       = pack_h2(accS[nf][0], accS[nf][1]);
      *(uint32_t*)&Pw[(g + 8) * AP + nf * 8 + 2 * t] = pack_h2(accS[nf][2], accS[nf][3]);
    }
    __syncwarp();

#pragma unroll
    for (int kcP = 0; kcP < 4; kcP++) {
      uint32_t aP[4];
      ldsm4(aP, pAddr + kcP * 32);
#pragma unroll
      for (int p = 0; p < 4; p++) {
        uint32_t bf[4];
        ldsm4t(bf, vAddr[p] + kcP * (16 * AP * 2));
        mma_f16(accO[2 * p + 0], aP, bf + 0);
        mma_f16(accO[2 * p + 1], aP, bf + 2);
      }
    }
    __syncwarp();
  }

  const float inv0 = 1.f / rowL0, inv1 = 1.f / rowL1;
  const int row0 = q0 + w * 16 + g;
#pragma unroll
  for (int nf = 0; nf < 8; nf++) {
    const int col = h * 64 + nf * 8 + t * 2;
    const size_t i0 = (size_t)(b * N_ + row0) * C_ + col;
    const size_t i1 = (size_t)(b * N_ + row0 + 8) * C_ + col;
    ((uint32_t*)g_att16)[i0 >> 1] = pack_h2(accO[nf][0] * inv0, accO[nf][1] * inv0);
    ((uint32_t*)g_att16)[i1 >> 1] = pack_h2(accO[nf][2] * inv1, accO[nf][3] * inv1);
  }
}

extern "C" void kernel_launch(void* const* d_in, const int* in_sizes, int n_in,
                              void* d_out, int out_size) {
  const float* x      = (const float*)d_in[0];
  const int*   pad    = (const int*)  d_in[1];
  const float* w_attn = (const float*)d_in[2];
  const float* b_attn = (const float*)d_in[3];
  const float* w_proj = (const float*)d_in[4];
  const float* b_proj = (const float*)d_in[5];
  float* out = (float*)d_out;

  // 0) prep: fp16 conversions / weight transposes
  cvt_x_kernel<<<(M_*C_/4 + 255) / 256, 256>>>(x);
  transpose_h_kernel<true> <<<dim3(2304/32, 768/32), dim3(32, 8)>>>(w_attn, 2304);
  transpose_h_kernel<false><<<dim3(768/32,  768/32), dim3(32, 8)>>>(w_proj, 768);
  // 1) QKV projection -> fp16 [B,H,N,D]  (CTA tile 256x128)
  mma_gemm<true><<<dim3(18, 32), 256>>>(b_attn, nullptr);
  // 2) fused attention -> fp16 [B,N,C]
  attn_mma<<<dim3(8, 96), 256>>>(pad);
  // 3) output projection -> fp32 d_out
  mma_gemm<false><<<dim3(6, 32), 256>>>(b_proj, out);
}

// round 15
// speedup vs baseline: 3.7842x; 1.0068x over previous
#include <cuda_runtime.h>
#include <cuda_fp16.h>
#include <math.h>
#include <stdint.h>

#define B_ 8
#define N_ 1024
#define C_ 768
#define H_ 12
#define D_ 64
#define M_ (B_*N_)   // 8192

// Scratch (allocation-free rule: __device__ globals), fp16 operands
__device__ __align__(16) __half g_x16[M_*C_];        // x, row-major [m][768]
__device__ __align__(16) __half g_wa16[3*C_*C_];     // w_attn^T [2304][768]
__device__ __align__(16) __half g_wp16[C_*C_];       // w_proj^T [768][768]
__device__ __align__(16) __half g_q16[B_*H_*N_*D_];  // [B,H,N,D]
__device__ __align__(16) __half g_k16[B_*H_*N_*D_];
__device__ __align__(16) __half g_v16[B_*H_*N_*D_];
__device__ __align__(16) __half g_att16[M_*C_];      // [B,N,C]

__device__ __forceinline__ uint32_t pack_h2(float x, float y) {
  __half2 h = __floats2half2_rn(x, y);
  return *reinterpret_cast<uint32_t*>(&h);
}

__device__ __forceinline__ void mma_f16(float* d, const uint32_t* a, const uint32_t* b) {
  asm volatile(
    "mma.sync.aligned.m16n8k16.row.col.f32.f16.f16.f32 "
    "{%0,%1,%2,%3}, {%4,%5,%6,%7}, {%8,%9}, {%0,%1,%2,%3};"
    : "+f"(d[0]), "+f"(d[1]), "+f"(d[2]), "+f"(d[3])
    : "r"(a[0]), "r"(a[1]), "r"(a[2]), "r"(a[3]), "r"(b[0]), "r"(b[1]));
}

__device__ __forceinline__ void ldsm4(uint32_t* r, uint32_t a) {
  asm volatile("ldmatrix.sync.aligned.m8n8.x4.shared.b16 {%0,%1,%2,%3}, [%4];"
    : "=r"(r[0]), "=r"(r[1]), "=r"(r[2]), "=r"(r[3]) : "r"(a));
}
__device__ __forceinline__ void ldsm4t(uint32_t* r, uint32_t a) {
  asm volatile("ldmatrix.sync.aligned.m8n8.x4.trans.shared.b16 {%0,%1,%2,%3}, [%4];"
    : "=r"(r[0]), "=r"(r[1]), "=r"(r[2]), "=r"(r[3]) : "r"(a));
}
__device__ __forceinline__ uint32_t smaddr(const void* p) {
  return (uint32_t)__cvta_generic_to_shared(p);
}
__device__ __forceinline__ void cp16(uint32_t dst, const void* src) {
  asm volatile("cp.async.cg.shared.global [%0], [%1], 16;" :: "r"(dst), "l"(src) : "memory");
}
#define CP_COMMIT() asm volatile("cp.async.commit_group;" ::: "memory")
template<int N> __device__ __forceinline__ void cp_wait() {
  asm volatile("cp.async.wait_group %0;" :: "n"(N) : "memory");
}

// ---------------------------------------------------------------------------
// Prep kernels
// ---------------------------------------------------------------------------
__global__ void cvt_x_kernel(const float* __restrict__ x) {
  const int i = blockIdx.x * 256 + threadIdx.x;
  const float4 v = ((const float4*)x)[i];
  uint2 o;
  o.x = pack_h2(v.x, v.y);
  o.y = pack_h2(v.z, v.w);
  ((uint2*)g_x16)[i] = o;
}

template<bool ATTN>   // src [768(k)][cols(n)] -> dst fp16 [n][k]
__global__ void transpose_h_kernel(const float* __restrict__ src, int cols) {
  __shared__ float tb[32][33];
  __half* dst = ATTN ? g_wa16 : g_wp16;
  const int cb = blockIdx.x * 32, rb = blockIdx.y * 32;
  const int x = threadIdx.x, y = threadIdx.y;
#pragma unroll
  for (int i = 0; i < 32; i += 8)
    tb[y + i][x] = src[(size_t)(rb + y + i) * cols + cb + x];
  __syncthreads();
#pragma unroll
  for (int i = 0; i < 32; i += 8)
    dst[(size_t)(cb + y + i) * 768 + rb + x] = __float2half_rn(tb[x][y + i]);
}

// ---------------------------------------------------------------------------
// fp16 GEMM, 64x64 warp tiles, cp.async 3-stage pipeline.
// CTA 256m x 128n, 8 warps (4m x 2n), K=16/stage.
// Dynamic smem 54KB: A[3][256*GP] | B[3][128*GP], pitch GP=24 halves.
// ---------------------------------------------------------------------------
#define GP 24
#define A_BUF_B (256 * GP * 2)   // 12288 bytes per A stage
#define B_BUF_B (128 * GP * 2)   // 6144 bytes per B stage
template<bool QKV>
__global__ __launch_bounds__(256) void mma_gemm(
    const float* __restrict__ bias, float* __restrict__ Out)
{
  extern __shared__ __half dsm[];
  __half* Adyn = dsm;                  // 3 * 6144 halves
  __half* Bdyn = dsm + 3 * 256 * GP;   // 3 * 3072 halves

  const int tid  = threadIdx.x;
  const int lane = tid & 31;
  const int w    = tid >> 5;
  const int wm   = w >> 1;
  const int wn   = w & 1;
  const int m0 = blockIdx.y * 256, n0 = blockIdx.x * 128;

  const __half* A16 = QKV ? g_x16 : g_att16;
  const __half* W16 = QKV ? g_wa16 : g_wp16;

  float acc[4][8][4];
#pragma unroll
  for (int i = 0; i < 4; i++)
#pragma unroll
    for (int j = 0; j < 8; j++)
#pragma unroll
      for (int q = 0; q < 4; q++) acc[i][j][q] = 0.f;

  // staging coordinates
  const int b_r = tid & 127, b_k8 = tid >> 7;
  const __half* aptr = A16 + (size_t)(m0 + tid) * 768;
  const __half* bptr = W16 + (size_t)(n0 + b_r) * 768 + b_k8 * 8;
  const uint32_t a_sm = smaddr(Adyn) + tid * GP * 2;
  const uint32_t b_sm = smaddr(Bdyn) + (b_r * GP + b_k8 * 8) * 2;

  auto issue = [&](int kt, int buf) {
    cp16(a_sm + buf * A_BUF_B,      aptr + kt * 16);
    cp16(a_sm + buf * A_BUF_B + 16, aptr + kt * 16 + 8);
    cp16(b_sm + buf * B_BUF_B,      bptr + kt * 16);
  };

  // ldmatrix lane addressing (relative to buffer 0)
  const int lrow = (lane & 7) + ((lane >> 3) & 1) * 8;
  const int lkc  = (lane >> 4) * 8;
  uint32_t aAddr[4], bAddr[4];
#pragma unroll
  for (int mf = 0; mf < 4; mf++)
    aAddr[mf] = smaddr(&Adyn[(wm * 64 + mf * 16 + lrow) * GP + lkc]);
  const int brow = 8 * (lane >> 4) + (lane & 7);
  const int bkc  = ((lane >> 3) & 1) * 8;
#pragma unroll
  for (int p = 0; p < 4; p++)
    bAddr[p] = smaddr(&Bdyn[(wn * 64 + p * 16 + brow) * GP + bkc]);

  // prologue: 2 stages in flight
  issue(0, 0); CP_COMMIT();
  issue(1, 1); CP_COMMIT();

  int cur = 0;
  for (int kt = 0; kt < 48; kt++) {
    if (kt < 47) cp_wait<1>(); else cp_wait<0>();
    __syncthreads();                       // stage kt visible; compute kt-1 done
    if (kt + 2 < 48) {
      const int nb = (cur == 0) ? 2 : cur - 1;   // (kt+2)%3
      issue(kt + 2, nb);
      CP_COMMIT();
    }

    const uint32_t aOff = (uint32_t)cur * A_BUF_B;
    const uint32_t bOff = (uint32_t)cur * B_BUF_B;
    uint32_t af[4][4];
#pragma unroll
    for (int mf = 0; mf < 4; mf++)
      ldsm4(af[mf], aAddr[mf] + aOff);
#pragma unroll
    for (int p = 0; p < 4; p++) {
      uint32_t bf[4];   // {b0_e, b1_e, b0_o, b1_o}
      ldsm4(bf, bAddr[p] + bOff);
#pragma unroll
      for (int mf = 0; mf < 4; mf++) {
        mma_f16(acc[mf][2 * p + 0], af[mf], bf + 0);
        mma_f16(acc[mf][2 * p + 1], af[mf], bf + 2);
      }
    }
    cur = (cur == 2) ? 0 : cur + 1;
  }

  // --- epilogue ---
  const int g = lane >> 2, tq = lane & 3;
#pragma unroll
  for (int mf = 0; mf < 4; mf++) {
    const int r0 = m0 + wm * 64 + mf * 16 + g;
#pragma unroll
    for (int nf = 0; nf < 8; nf++) {
      const int col = n0 + wn * 64 + nf * 8 + tq * 2;
      const float bx = bias[col], by = bias[col + 1];
#pragma unroll
      for (int half_ = 0; half_ < 2; half_++) {
        const int r = r0 + half_ * 8;
        const float ox = acc[mf][nf][half_ * 2 + 0] + bx;
        const float oy = acc[mf][nf][half_ * 2 + 1] + by;
        if (QKV) {
          const int bb = r >> 10, t = r & 1023;
          const int which = col / 768;
          const int c = col - which * 768;
          const int hh = c >> 6, d = c & 63;
          __half* dst = (which == 0) ? g_q16 : (which == 1) ? g_k16 : g_v16;
          const size_t idx = ((size_t)((bb * 12 + hh) * 1024 + t)) * 64 + d;
          ((uint32_t*)dst)[idx >> 1] = pack_h2(ox, oy);
        } else {
          float2 o; o.x = ox; o.y = oy;
          *(float2*)&Out[(size_t)r * 768 + col] = o;
        }
      }
    }
  }
}

// ---------------------------------------------------------------------------
// fp16 flash attention, cp.async double-buffered K/V.
// CTA: 128 Q-rows of one (b,h); 8 warps; warp w owns rows [16w,16w+16).
// Dynamic smem 54KB: sQ[128*AP] | sK[2][64*AP] | sV[2][64*AP], AP=72.
// ---------------------------------------------------------------------------
#define AP 72
#define KV_BUF_B (64 * AP * 2)   // 9216 bytes per K (or V) stage
__global__ __launch_bounds__(256) void attn_mma(const int* __restrict__ pad_mask)
{
  extern __shared__ __half dsm[];
  __half* sQ = dsm;                       // 9216 halves (P aliases per-warp rows)
  __half* sK = dsm + 128 * AP;            // 2 buffers
  __half* sV = dsm + 128 * AP + 2 * 64 * AP;

  const int tid  = threadIdx.x;
  const int lane = tid & 31;
  const int w    = tid >> 5;
  const int g    = lane >> 2;
  const int t    = lane & 3;
  const int bh = blockIdx.y;
  const int b  = bh / 12, h = bh % 12;
  const int q0 = blockIdx.x << 7;

  const __half* Qg = g_q16 + (size_t)bh * (N_*D_) + (size_t)q0 * D_;
  const __half* Kg = g_k16 + (size_t)bh * (N_*D_);
  const __half* Vg = g_v16 + (size_t)bh * (N_*D_);

  // staging coordinates for K/V (2 chunks each per thread)
  int kv_soff[2], kv_goff[2];
#pragma unroll
  for (int it = 0; it < 2; it++) {
    const int idx = tid + it * 256;
    const int r = idx >> 3, d8 = idx & 7;
    kv_soff[it] = (r * AP + d8 * 8) * 2;   // bytes
    kv_goff[it] = r * 64 + d8 * 8;         // halves within tile
  }
  const uint32_t k_sm = smaddr(sK);
  const uint32_t v_sm = smaddr(sV);
  auto issueKV = [&](int kt, int buf) {
#pragma unroll
    for (int it = 0; it < 2; it++) {
      cp16(k_sm + buf * KV_BUF_B + kv_soff[it], Kg + (size_t)kt * 64 * 64 + kv_goff[it]);
      cp16(v_sm + buf * KV_BUF_B + kv_soff[it], Vg + (size_t)kt * 64 * 64 + kv_goff[it]);
    }
  };

  // --- stage Q row-major (once) + issue KV stage 0 ---
  issueKV(0, 0); CP_COMMIT();
#pragma unroll
  for (int it = 0; it < 4; it++) {
    const int idx = tid + it * 256;
    const int r = idx >> 3, d8 = idx & 7;
    *(uint4*)&sQ[r * AP + d8 * 8] = *(const uint4*)(Qg + (size_t)r * 64 + d8 * 8);
  }
  __syncthreads();

  // --- hoist Q fragments (warp-private rows 16w..16w+15) ---
  const int lrow = (lane & 7) + ((lane >> 3) & 1) * 8;
  const uint32_t qAddr = smaddr(&sQ[(w * 16 + lrow) * AP + (lane >> 4) * 8]);
  uint32_t aQ[4][4];
#pragma unroll
  for (int kc = 0; kc < 4; kc++)
    ldsm4(aQ[kc], qAddr + kc * 32);

  const int brow = 8 * (lane >> 4) + (lane & 7);
  const int bkc  = ((lane >> 3) & 1) * 8;
  uint32_t kAddr[4], vAddr[4];
#pragma unroll
  for (int p = 0; p < 4; p++) {
    kAddr[p] = smaddr(&sK[(p * 16 + brow) * AP + bkc]);
    vAddr[p] = smaddr(&sV[(8 * ((lane >> 3) & 1) + (lane & 7)) * AP + p * 16 + (lane >> 4) * 8]);
  }
  __half* Pw = &sQ[w * 16 * AP];
  const uint32_t pAddr = smaddr(&Pw[lrow * AP + (lane >> 4) * 8]);

  const bool mz0 = (pad_mask[b * N_ + q0 + w * 16 + g] == 0);
  const bool mz1 = (pad_mask[b * N_ + q0 + w * 16 + g + 8] == 0);

  float accO[8][4];
#pragma unroll
  for (int nf = 0; nf < 8; nf++)
#pragma unroll
    for (int j = 0; j < 4; j++) accO[nf][j] = 0.f;
  float rowM0 = -INFINITY, rowM1 = -INFINITY, rowL0 = 0.f, rowL1 = 0.f;

  for (int kt = 0; kt < 16; kt++) {
    cp_wait<0>();
    __syncthreads();                       // stage kt visible; compute kt-1 done
    if (kt + 1 < 16) { issueKV(kt + 1, (kt + 1) & 1); CP_COMMIT(); }
    const uint32_t kvOff = (uint32_t)(kt & 1) * KV_BUF_B;

    // --- S = Q K^T ---
    float accS[8][4];
#pragma unroll
    for (int nf = 0; nf < 8; nf++)
#pragma unroll
      for (int j = 0; j < 4; j++) accS[nf][j] = 0.f;
#pragma unroll
    for (int kc = 0; kc < 4; kc++) {
#pragma unroll
      for (int p = 0; p < 4; p++) {
        uint32_t bf[4];
        ldsm4(bf, kAddr[p] + kvOff + kc * 32);
        mma_f16(accS[2 * p + 0], aQ[kc], bf + 0);
        mma_f16(accS[2 * p + 1], aQ[kc], bf + 2);
      }
    }

    // --- online softmax (warp-local; rows g and g+8) ---
    float mx0 = -INFINITY, mx1 = -INFINITY;
#pragma unroll
    for (int nf = 0; nf < 8; nf++) {
      accS[nf][0] = mz0 ? -INFINITY : accS[nf][0] * 0.125f;
      accS[nf][1] = mz0 ? -INFINITY : accS[nf][1] * 0.125f;
      accS[nf][2] = mz1 ? -INFINITY : accS[nf][2] * 0.125f;
      accS[nf][3] = mz1 ? -INFINITY : accS[nf][3] * 0.125f;
      mx0 = fmaxf(mx0, fmaxf(accS[nf][0], accS[nf][1]));
      mx1 = fmaxf(mx1, fmaxf(accS[nf][2], accS[nf][3]));
    }
#pragma unroll
    for (int o = 1; o <= 2; o <<= 1) {
      mx0 = fmaxf(mx0, __shfl_xor_sync(0xffffffffu, mx0, o));
      mx1 = fmaxf(mx1, __shfl_xor_sync(0xffffffffu, mx1, o));
    }
    const float mn0 = fmaxf(rowM0, mx0), mn1 = fmaxf(rowM1, mx1);
    const float fac0 = __expf(rowM0 - mn0), fac1 = __expf(rowM1 - mn1);
    rowM0 = mn0; rowM1 = mn1;
    float sum0 = 0.f, sum1 = 0.f;
#pragma unroll
    for (int nf = 0; nf < 8; nf++) {
      accS[nf][0] = __expf(accS[nf][0] - mn0);
      accS[nf][1] = __expf(accS[nf][1] - mn0);
      accS[nf][2] = __expf(accS[nf][2] - mn1);
      accS[nf][3] = __expf(accS[nf][3] - mn1);
      sum0 += accS[nf][0] + accS[nf][1];
      sum1 += accS[nf][2] + accS[nf][3];
    }
#pragma unroll
    for (int o = 1; o <= 2; o <<= 1) {
      sum0 += __shfl_xor_sync(0xffffffffu, sum0, o);
      sum1 += __shfl_xor_sync(0xffffffffu, sum1, o);
    }
    rowL0 = rowL0 * fac0 + sum0;
    rowL1 = rowL1 * fac1 + sum1;
#pragma unroll
    for (int nf = 0; nf < 8; nf++) {
      accO[nf][0] *= fac0; accO[nf][1] *= fac0;
      accO[nf][2] *= fac1; accO[nf][3] *= fac1;
    }

    // --- store P row-major (conflict-free) ---
#pragma unroll
    for (int nf = 0; nf < 8; nf++) {
      *(uint32_t*)&Pw[g * AP + nf * 8 + 2 * t]       = pack_h2(accS[nf][0], accS[nf][1]);
      *(uint32_t*)&Pw[(g + 8) * AP + nf * 8 + 2 * t] = pack_h2(accS[nf][2], accS[nf][3]);
    }
    __syncwarp();

    // --- O += P V ---
#pragma unroll
    for (int kcP = 0; kcP < 4; kcP++) {
      uint32_t aP[4];
      ldsm4(aP, pAddr + kcP * 32);
#pragma unroll
      for (int p = 0; p < 4; p++) {
        uint32_t bf[4];
        ldsm4t(bf, vAddr[p] + kvOff + kcP * (16 * AP * 2));
        mma_f16(accO[2 * p + 0], aP, bf + 0);
        mma_f16(accO[2 * p + 1], aP, bf + 2);
      }
    }
    __syncwarp();
  }

  // --- epilogue: normalize + write g_att16[B,N,C] ---
  const float inv0 = 1.f / rowL0, inv1 = 1.f / rowL1;
  const int row0 = q0 + w * 16 + g;
#pragma unroll
  for (int nf = 0; nf < 8; nf++) {
    const int col = h * 64 + nf * 8 + t * 2;
    const size_t i0 = (size_t)(b * N_ + row0) * C_ + col;
    const size_t i1 = (size_t)(b * N_ + row0 + 8) * C_ + col;
    ((uint32_t*)g_att16)[i0 >> 1] = pack_h2(accO[nf][0] * inv0, accO[nf][1] * inv0);
    ((uint32_t*)g_att16)[i1 >> 1] = pack_h2(accO[nf][2] * inv1, accO[nf][3] * inv1);
  }
}

extern "C" void kernel_launch(void* const* d_in, const int* in_sizes, int n_in,
                              void* d_out, int out_size) {
  const float* x      = (const float*)d_in[0];
  const int*   pad    = (const int*)  d_in[1];
  const float* w_attn = (const float*)d_in[2];
  const float* b_attn = (const float*)d_in[3];
  const float* w_proj = (const float*)d_in[4];
  const float* b_proj = (const float*)d_in[5];
  float* out = (float*)d_out;

  const int gemm_smem = 3 * (A_BUF_B + B_BUF_B);              // 55296 B
  const int attn_smem = (128 * AP + 4 * 64 * AP) * 2;         // 55296 B
  cudaFuncSetAttribute(mma_gemm<true>,  cudaFuncAttributeMaxDynamicSharedMemorySize, gemm_smem);
  cudaFuncSetAttribute(mma_gemm<false>, cudaFuncAttributeMaxDynamicSharedMemorySize, gemm_smem);
  cudaFuncSetAttribute(attn_mma, cudaFuncAttributeMaxDynamicSharedMemorySize, attn_smem);

  // 0) prep: fp16 conversions / weight transposes
  cvt_x_kernel<<<(M_*C_/4 + 255) / 256, 256>>>(x);
  transpose_h_kernel<true> <<<dim3(2304/32, 768/32), dim3(32, 8)>>>(w_attn, 2304);
  transpose_h_kernel<false><<<dim3(768/32,  768/32), dim3(32, 8)>>>(w_proj, 768);
  // 1) QKV projection -> fp16 [B,H,N,D]  (CTA tile 256x128)
  mma_gemm<true><<<dim3(18, 32), 256, gemm_smem>>>(b_attn, nullptr);
  // 2) fused attention -> fp16 [B,N,C]
  attn_mma<<<dim3(8, 96), 256, attn_smem>>>(pad);
  // 3) output projection -> fp32 d_out
  mma_gemm<false><<<dim3(6, 32), 256, gemm_smem>>>(b_proj, out);
}